// round 7
// baseline (speedup 1.0000x reference)
#include <cuda_runtime.h>
#include <cstddef>

#define NN 100000

// Scratch (device globals, referenced directly from device code)
__device__ float g_deg[NN];                 // degree, then overwritten with 1/max(deg,1)
__device__ float g_agg[(size_t)NN * 128];
__device__ float g_y[(size_t)NN * 128];
__device__ float g_h[(size_t)NN * 128];
__device__ int   g_is64;

// ---------------------------------------------------------------------------
// dtype detection (int64 values < 1e5 have zero high words)
// ---------------------------------------------------------------------------
__global__ void detect_kernel(const int* __restrict__ ei32) {
    if (blockIdx.x == 0 && threadIdx.x == 0) {
        int is64 = 1;
        for (int i = 0; i < 64; i++)
            if (ei32[2 * i + 1] != 0) { is64 = 0; break; }
        g_is64 = is64;
    }
}

__device__ __forceinline__ int load_idx(const void* ei, int pos, int nE,
                                        int half, int n) {
    size_t idx = (size_t)half * nE + pos;
    long long v;
    if (g_is64) v = ((const long long*)ei)[idx];
    else        v = ((const int*)ei)[idx];
    if (v < 0) v = 0;
    if (v >= n) v = n - 1;
    return (int)v;
}

// ---------------------------------------------------------------------------
// zero kernels
// ---------------------------------------------------------------------------
__global__ void zero_deg_kernel(int n4) {
    int i = blockIdx.x * blockDim.x + threadIdx.x;
    if (i < n4) ((float4*)g_deg)[i] = make_float4(0.f, 0.f, 0.f, 0.f);
}
__global__ void zero_agg_kernel(int n4) {
    int i = blockIdx.x * blockDim.x + threadIdx.x;
    if (i < n4) ((float4*)g_agg)[i] = make_float4(0.f, 0.f, 0.f, 0.f);
}

// deg -> 1/max(deg,1), in place
__global__ void rdeg_kernel(int n) {
    int i = blockIdx.x * blockDim.x + threadIdx.x;
    if (i < n) g_deg[i] = 1.0f / fmaxf(g_deg[i], 1.0f);
}

// ---------------------------------------------------------------------------
// scatter-add: D/4 lanes per edge; float4 gather + red.global.add.v4.f32.
// USEGY: gather from g_y (layer 2) instead of the Y arg (layer 1 uses x).
// FUSEDEG: lane 0 also accumulates degree (layer 1 only).
// ---------------------------------------------------------------------------
template <int D, bool USEGY, bool FUSEDEG>
__global__ void scatter_kernel(const float* __restrict__ Yarg,
                               const void* __restrict__ ei, int nE, int n) {
    constexpr int LPE = D / 4;
    long long t = (long long)blockIdx.x * blockDim.x + threadIdx.x;
    int e = (int)(t / LPE);
    int lane = (int)(t % LPE);
    if (e >= nE) return;
    const float* Y = USEGY ? (const float*)g_y : Yarg;
    int src = load_idx(ei, e, nE, 0, n);
    int dst = load_idx(ei, e, nE, 1, n);
    if (FUSEDEG && lane == 0) atomicAdd(&g_deg[dst], 1.0f);
    float4 v = ((const float4*)(Y + (size_t)src * D))[lane];
    float* p = g_agg + (size_t)dst * D + lane * 4;
    asm volatile("red.global.add.v4.f32 [%0], {%1,%2,%3,%4};"
                 :: "l"(p), "f"(v.x), "f"(v.y), "f"(v.z), "f"(v.w)
                 : "memory");
}

// ---------------------------------------------------------------------------
// GEMM 1 (fused layer 1):  g_h = relu([rdeg*agg | x] @ [W1l ; W1r] + b1)
// BM=64, BN=128, K=256 (two 128-sources), KC=32, 256 threads.
// Thread tile 8x4: tx = tid%32 (4 cols), ty = tid/32 (8 rows).
// sA[m][k] row-major (A LDS is warp-broadcast), sW[k][n] (float4 LDS).
// ---------------------------------------------------------------------------
__global__ void gemm1_kernel(const float* __restrict__ x,
                             const float* __restrict__ W1l,
                             const float* __restrict__ W1r,
                             const float* __restrict__ b1, int n) {
    constexpr int BM = 64, BN = 128, KC = 32, KCP = 36, BNP = BN + 4;
    __shared__ float sA[BM * KCP];   // 9.2 KB
    __shared__ float sW[KC * BNP];   // 16.9 KB
    const int tid = threadIdx.x;
    const int node0 = blockIdx.x * BM;
    const int tx = tid & 31;   // 32 column groups
    const int ty = tid >> 5;   // 8 row groups

    float acc[8][4];
#pragma unroll
    for (int j = 0; j < 8; j++)
#pragma unroll
        for (int v = 0; v < 4; v++) acc[j][v] = 0.f;

    for (int kc = 0; kc < 256; kc += KC) {
        const bool first = kc < 128;
        const int koff = first ? kc : kc - 128;
        const float* Abase = first ? (const float*)g_agg : x;
        const float* Wbase = (first ? W1l : W1r) + (size_t)koff * BN;

        // stage A: BM x KC (float4, row-coalesced), scale agg rows by rdeg
        for (int t = tid; t < BM * (KC / 4); t += 256) {
            int m = t >> 3, kq = t & 7;
            int node = node0 + m;
            float4 v = make_float4(0.f, 0.f, 0.f, 0.f);
            if (node < n) {
                v = ((const float4*)(Abase + (size_t)node * 128 + koff))[kq];
                if (first) {
                    float r = g_deg[node];   // holds rdeg
                    v.x *= r; v.y *= r; v.z *= r; v.w *= r;
                }
            }
            *(float4*)(sA + m * KCP + kq * 4) = v;
        }
        // stage W: KC x BN
        for (int t = tid; t < KC * (BN / 4); t += 256) {
            int k = t / (BN / 4), nq = t % (BN / 4);
            *(float4*)(sW + k * BNP + nq * 4) =
                ((const float4*)(Wbase + (size_t)k * BN))[nq];
        }
        __syncthreads();

#pragma unroll 8
        for (int k = 0; k < KC; k++) {
            float4 w = *(const float4*)(sW + k * BNP + tx * 4);
#pragma unroll
            for (int j = 0; j < 8; j++) {
                float a = sA[(ty * 8 + j) * KCP + k];
                acc[j][0] = fmaf(a, w.x, acc[j][0]);
                acc[j][1] = fmaf(a, w.y, acc[j][1]);
                acc[j][2] = fmaf(a, w.z, acc[j][2]);
                acc[j][3] = fmaf(a, w.w, acc[j][3]);
            }
        }
        __syncthreads();
    }

    float4 bb = *(const float4*)(b1 + tx * 4);
#pragma unroll
    for (int j = 0; j < 8; j++) {
        int node = node0 + ty * 8 + j;
        if (node >= n) break;
        float4 r;
        r.x = fmaxf(acc[j][0] + bb.x, 0.f);
        r.y = fmaxf(acc[j][1] + bb.y, 0.f);
        r.z = fmaxf(acc[j][2] + bb.z, 0.f);
        r.w = fmaxf(acc[j][3] + bb.w, 0.f);
        *(float4*)(g_h + (size_t)node * 128 + tx * 4) = r;
    }
}

// ---------------------------------------------------------------------------
// GEMM 2/3 (layer 2): C[n,64] = g_h[n,128] @ W[128,64]  (+ optional epilogue)
// MODE 0: C = g_y (pre-aggregation product).  MODE 1: C = out arg, epilogue
//         adds g_agg*rdeg + b2.
// BM=128, BN=64, KC=32, 256 threads; tx = tid%16 (4 cols), ty = tid/16.
// ---------------------------------------------------------------------------
template <int MODE>
__global__ void gemm2_kernel(const float* __restrict__ W,
                             const float* __restrict__ b2,
                             float* __restrict__ Cout, int n) {
    constexpr int BM = 128, BN = 64, KC = 32, KCP = 36, BNP = BN + 4;
    __shared__ float sA[BM * KCP];   // 18 KB
    __shared__ float sW[KC * BNP];   // 8.5 KB
    const int tid = threadIdx.x;
    const int node0 = blockIdx.x * BM;
    const int tx = tid & 15;   // 16 column groups
    const int ty = tid >> 4;   // 16 row groups

    float acc[8][4];
#pragma unroll
    for (int j = 0; j < 8; j++)
#pragma unroll
        for (int v = 0; v < 4; v++) acc[j][v] = 0.f;

    for (int kc = 0; kc < 128; kc += KC) {
        for (int t = tid; t < BM * (KC / 4); t += 256) {
            int m = t >> 3, kq = t & 7;
            int node = node0 + m;
            float4 v = make_float4(0.f, 0.f, 0.f, 0.f);
            if (node < n)
                v = ((const float4*)(g_h + (size_t)node * 128 + kc))[kq];
            *(float4*)(sA + m * KCP + kq * 4) = v;
        }
        for (int t = tid; t < KC * (BN / 4); t += 256) {
            int k = t / (BN / 4), nq = t % (BN / 4);
            *(float4*)(sW + k * BNP + nq * 4) =
                ((const float4*)(W + (size_t)(kc + k) * BN))[nq];
        }
        __syncthreads();

#pragma unroll 8
        for (int k = 0; k < KC; k++) {
            float4 w = *(const float4*)(sW + k * BNP + tx * 4);
#pragma unroll
            for (int j = 0; j < 8; j++) {
                float a = sA[(ty * 8 + j) * KCP + k];
                acc[j][0] = fmaf(a, w.x, acc[j][0]);
                acc[j][1] = fmaf(a, w.y, acc[j][1]);
                acc[j][2] = fmaf(a, w.z, acc[j][2]);
                acc[j][3] = fmaf(a, w.w, acc[j][3]);
            }
        }
        __syncthreads();
    }

    float* C = (MODE == 0) ? (float*)g_y : Cout;
    float4 bb = (MODE == 1) ? *(const float4*)(b2 + tx * 4)
                            : make_float4(0.f, 0.f, 0.f, 0.f);
#pragma unroll
    for (int j = 0; j < 8; j++) {
        int node = node0 + ty * 8 + j;
        if (node >= n) break;
        float4 r = make_float4(acc[j][0], acc[j][1], acc[j][2], acc[j][3]);
        if (MODE == 1) {
            float rd = g_deg[node];  // rdeg
            float4 ag = *(const float4*)(g_agg + (size_t)node * 64 + tx * 4);
            r.x += ag.x * rd + bb.x;
            r.y += ag.y * rd + bb.y;
            r.z += ag.z * rd + bb.z;
            r.w += ag.w * rd + bb.w;
        }
        *(float4*)(C + (size_t)node * 64 + tx * 4) = r;
    }
}

// ---------------------------------------------------------------------------
// launch
// ---------------------------------------------------------------------------
extern "C" void kernel_launch(void* const* d_in, const int* in_sizes, int n_in,
                              void* d_out, int out_size) {
    const float* x   = (const float*)d_in[0];
    const void*  ei  = d_in[1];
    const float* W1l = (const float*)d_in[2];
    const float* W1r = (const float*)d_in[3];
    const float* b1  = (const float*)d_in[4];
    const float* W2l = (const float*)d_in[5];
    const float* W2r = (const float*)d_in[6];
    const float* b2  = (const float*)d_in[7];
    float* out = (float*)d_out;

    const int n  = in_sizes[0] / 128;   // 100000
    const int nE = in_sizes[1] / 2;     // 1600000

    detect_kernel<<<1, 32>>>((const int*)ei);

    zero_deg_kernel<<<(n / 4 + 255) / 256, 256>>>(n / 4);
    zero_agg_kernel<<<(n * 32 + 255) / 256, 256>>>(n * 32);

    // ---- Layer 1: aggregate raw x (deg fused at lane 0) ----
    {
        long long threads = (long long)nE * 32;
        scatter_kernel<128, false, true>
            <<<(unsigned)((threads + 255) / 256), 256>>>(x, ei, nE, n);
    }
    rdeg_kernel<<<(n + 255) / 256, 256>>>(n);

    // h = relu([rdeg*agg | x] @ [W1l;W1r] + b1)
    gemm1_kernel<<<(n + 63) / 64, 256>>>(x, W1l, W1r, b1, n);

    // ---- Layer 2 ----
    zero_agg_kernel<<<(n * 16 + 255) / 256, 256>>>(n * 16);
    // g_y = h @ W2l   (pre-multiply: mean is linear)
    gemm2_kernel<0><<<(n + 127) / 128, 256>>>(W2l, nullptr, nullptr, n);
    {
        long long threads = (long long)nE * 16;
        scatter_kernel<64, true, false>
            <<<(unsigned)((threads + 255) / 256), 256>>>(nullptr, ei, nE, n);
    }
    // out = h @ W2r + rdeg*agg + b2
    gemm2_kernel<1><<<(n + 127) / 128, 256>>>(W2r, b2, out, n);
}

// round 8
// speedup vs baseline: 1.5961x; 1.5961x over previous
#include <cuda_runtime.h>
#include <cstddef>

#define NN 100000
#define EE 1600000

// Scratch (device globals, referenced directly from device code)
__device__ float g_deg[NN];                 // degree, then 1/max(deg,1)
__device__ float g_agg[(size_t)NN * 128];
__device__ float g_y[(size_t)NN * 128];
__device__ float g_h[(size_t)NN * 128];
__device__ int2  g_edges[EE];               // clamped (src, dst)
__device__ int   g_is64;

// packed f32x2 FMA (Blackwell FFMA2 — only reachable via PTX)
#define FFMA2(d, a, b, c) \
    asm("fma.rn.f32x2 %0, %1, %2, %3;" : "=l"(d) : "l"(a), "l"(b), "l"(c))
#define PACK2(d, s) \
    asm("mov.b64 %0, {%1, %1};" : "=l"(d) : "r"(s))

// ---------------------------------------------------------------------------
// dtype detection (int64 values < 1e5 have zero high words)
// ---------------------------------------------------------------------------
__global__ void detect_kernel(const int* __restrict__ ei32) {
    if (blockIdx.x == 0 && threadIdx.x == 0) {
        int is64 = 1;
        for (int i = 0; i < 64; i++)
            if (ei32[2 * i + 1] != 0) { is64 = 0; break; }
        g_is64 = is64;
    }
}

// ---------------------------------------------------------------------------
// edge conversion: either dtype -> clamped int2; fuses degree accumulation
// ---------------------------------------------------------------------------
__global__ void convert_kernel(const void* __restrict__ ei, int nE, int n) {
    int e = blockIdx.x * blockDim.x + threadIdx.x;
    if (e >= nE) return;
    long long s, d;
    if (g_is64) {
        s = ((const long long*)ei)[e];
        d = ((const long long*)ei)[(size_t)nE + e];
    } else {
        s = ((const int*)ei)[e];
        d = ((const int*)ei)[(size_t)nE + e];
    }
    if (s < 0) s = 0; if (s >= n) s = n - 1;
    if (d < 0) d = 0; if (d >= n) d = n - 1;
    g_edges[e] = make_int2((int)s, (int)d);
    atomicAdd(&g_deg[(int)d], 1.0f);
}

// ---------------------------------------------------------------------------
// zero / rdeg
// ---------------------------------------------------------------------------
__global__ void zero_deg_kernel(int n4) {
    int i = blockIdx.x * blockDim.x + threadIdx.x;
    if (i < n4) ((float4*)g_deg)[i] = make_float4(0.f, 0.f, 0.f, 0.f);
}
__global__ void zero_agg_kernel(int n4) {
    int i = blockIdx.x * blockDim.x + threadIdx.x;
    if (i < n4) ((float4*)g_agg)[i] = make_float4(0.f, 0.f, 0.f, 0.f);
}
__global__ void rdeg_kernel(int n) {
    int i = blockIdx.x * blockDim.x + threadIdx.x;
    if (i < n) g_deg[i] = 1.0f / fmaxf(g_deg[i], 1.0f);
}

// ---------------------------------------------------------------------------
// scatter-add from precomputed edges.
// D=128: one warp per edge (32 lanes x float4).
// D=64:  half-warp per edge (16 lanes x float4).
// Gather from Y (x for layer 1, g_y for layer 2), red.v4 into g_agg.
// ---------------------------------------------------------------------------
template <int D, bool USEGY>
__global__ void scatter_kernel(const float* __restrict__ Yarg, int nE) {
    constexpr int LPE = D / 4;                    // 32 or 16
    constexpr int EPW = 32 / LPE;                 // edges per warp: 1 or 2
    const int tid = threadIdx.x;
    const int warp = (blockIdx.x * blockDim.x + tid) >> 5;
    const int lane = tid & 31;
    const int sub = lane / LPE;                   // 0 (or 0/1 for D=64)
    const int l = lane % LPE;
    const int e = warp * EPW + sub;
    if (e >= nE) return;
    const float* Y = USEGY ? (const float*)g_y : Yarg;
    int2 ed = g_edges[e];                          // broadcast load
    float4 v = ((const float4*)(Y + (size_t)ed.x * D))[l];
    float* p = g_agg + (size_t)ed.y * D + l * 4;
    asm volatile("red.global.add.v4.f32 [%0], {%1,%2,%3,%4};"
                 :: "l"(p), "f"(v.x), "f"(v.y), "f"(v.z), "f"(v.w)
                 : "memory");
}

// ---------------------------------------------------------------------------
// GEMM 1 (fused layer 1):  g_h = relu([rdeg*agg | x] @ [W1l ; W1r] + b1)
// BM=64, BN=128, K=256 (two 128-sources), KC=32, 256 threads.
// Thread tile 8 rows x 4 cols; f32x2 packed FMA inner loop.
// ---------------------------------------------------------------------------
__global__ void gemm1_kernel(const float* __restrict__ x,
                             const float* __restrict__ W1l,
                             const float* __restrict__ W1r,
                             const float* __restrict__ b1, int n) {
    constexpr int BM = 64, BN = 128, KC = 32, KCP = 36, BNP = BN + 4;
    __shared__ float sA[BM * KCP];
    __shared__ float sW[KC * BNP];
    const int tid = threadIdx.x;
    const int node0 = blockIdx.x * BM;
    const int tx = tid & 31;
    const int ty = tid >> 5;

    unsigned long long acc0[8], acc1[8];          // cols {0,1} and {2,3}
#pragma unroll
    for (int j = 0; j < 8; j++) { acc0[j] = 0ull; acc1[j] = 0ull; }

    for (int kc = 0; kc < 256; kc += KC) {
        const bool first = kc < 128;
        const int koff = first ? kc : kc - 128;
        const float* Abase = first ? (const float*)g_agg : x;
        const float* Wbase = (first ? W1l : W1r) + (size_t)koff * BN;

        for (int t = tid; t < BM * (KC / 4); t += 256) {
            int m = t >> 3, kq = t & 7;
            int node = node0 + m;
            float4 v = make_float4(0.f, 0.f, 0.f, 0.f);
            if (node < n) {
                v = ((const float4*)(Abase + (size_t)node * 128 + koff))[kq];
                if (first) {
                    float r = g_deg[node];        // rdeg
                    v.x *= r; v.y *= r; v.z *= r; v.w *= r;
                }
            }
            *(float4*)(sA + m * KCP + kq * 4) = v;
        }
        for (int t = tid; t < KC * (BN / 4); t += 256) {
            int k = t / (BN / 4), nq = t % (BN / 4);
            *(float4*)(sW + k * BNP + nq * 4) =
                ((const float4*)(Wbase + (size_t)k * BN))[nq];
        }
        __syncthreads();

#pragma unroll 8
        for (int k = 0; k < KC; k++) {
            ulonglong2 w = *(const ulonglong2*)(sW + k * BNP + tx * 4);
#pragma unroll
            for (int j = 0; j < 8; j++) {
                float a = sA[(ty * 8 + j) * KCP + k];
                unsigned long long aa;
                PACK2(aa, __float_as_uint(a));
                FFMA2(acc0[j], aa, w.x, acc0[j]);
                FFMA2(acc1[j], aa, w.y, acc1[j]);
            }
        }
        __syncthreads();
    }

    float4 bb = *(const float4*)(b1 + tx * 4);
#pragma unroll
    for (int j = 0; j < 8; j++) {
        int node = node0 + ty * 8 + j;
        if (node >= n) break;
        float4 r;
        r.x = fmaxf(__uint_as_float((unsigned)acc0[j]) + bb.x, 0.f);
        r.y = fmaxf(__uint_as_float((unsigned)(acc0[j] >> 32)) + bb.y, 0.f);
        r.z = fmaxf(__uint_as_float((unsigned)acc1[j]) + bb.z, 0.f);
        r.w = fmaxf(__uint_as_float((unsigned)(acc1[j] >> 32)) + bb.w, 0.f);
        *(float4*)(g_h + (size_t)node * 128 + tx * 4) = r;
    }
}

// ---------------------------------------------------------------------------
// GEMM 2/3 (layer 2): C[n,64] = g_h[n,128] @ W[128,64]  (+ optional epilogue)
// MODE 0: C = g_y.  MODE 1: C = out arg, adds g_agg*rdeg + b2.
// BM=128, BN=64, KC=32, 256 threads; 8 rows x 4 cols; f32x2 inner loop.
// ---------------------------------------------------------------------------
template <int MODE>
__global__ void gemm2_kernel(const float* __restrict__ W,
                             const float* __restrict__ b2,
                             float* __restrict__ Cout, int n) {
    constexpr int BM = 128, BN = 64, KC = 32, KCP = 36, BNP = BN + 4;
    __shared__ float sA[BM * KCP];
    __shared__ float sW[KC * BNP];
    const int tid = threadIdx.x;
    const int node0 = blockIdx.x * BM;
    const int tx = tid & 15;
    const int ty = tid >> 4;

    unsigned long long acc0[8], acc1[8];
#pragma unroll
    for (int j = 0; j < 8; j++) { acc0[j] = 0ull; acc1[j] = 0ull; }

    for (int kc = 0; kc < 128; kc += KC) {
        for (int t = tid; t < BM * (KC / 4); t += 256) {
            int m = t >> 3, kq = t & 7;
            int node = node0 + m;
            float4 v = make_float4(0.f, 0.f, 0.f, 0.f);
            if (node < n)
                v = ((const float4*)(g_h + (size_t)node * 128 + kc))[kq];
            *(float4*)(sA + m * KCP + kq * 4) = v;
        }
        for (int t = tid; t < KC * (BN / 4); t += 256) {
            int k = t / (BN / 4), nq = t % (BN / 4);
            *(float4*)(sW + k * BNP + nq * 4) =
                ((const float4*)(W + (size_t)(kc + k) * BN))[nq];
        }
        __syncthreads();

#pragma unroll 8
        for (int k = 0; k < KC; k++) {
            ulonglong2 w = *(const ulonglong2*)(sW + k * BNP + tx * 4);
#pragma unroll
            for (int j = 0; j < 8; j++) {
                float a = sA[(ty * 8 + j) * KCP + k];
                unsigned long long aa;
                PACK2(aa, __float_as_uint(a));
                FFMA2(acc0[j], aa, w.x, acc0[j]);
                FFMA2(acc1[j], aa, w.y, acc1[j]);
            }
        }
        __syncthreads();
    }

    float* C = (MODE == 0) ? (float*)g_y : Cout;
    float4 bb = (MODE == 1) ? *(const float4*)(b2 + tx * 4)
                            : make_float4(0.f, 0.f, 0.f, 0.f);
#pragma unroll
    for (int j = 0; j < 8; j++) {
        int node = node0 + ty * 8 + j;
        if (node >= n) break;
        float4 r;
        r.x = __uint_as_float((unsigned)acc0[j]);
        r.y = __uint_as_float((unsigned)(acc0[j] >> 32));
        r.z = __uint_as_float((unsigned)acc1[j]);
        r.w = __uint_as_float((unsigned)(acc1[j] >> 32));
        if (MODE == 1) {
            float rd = g_deg[node];
            float4 ag = *(const float4*)(g_agg + (size_t)node * 64 + tx * 4);
            r.x += ag.x * rd + bb.x;
            r.y += ag.y * rd + bb.y;
            r.z += ag.z * rd + bb.z;
            r.w += ag.w * rd + bb.w;
        }
        *(float4*)(C + (size_t)node * 64 + tx * 4) = r;
    }
}

// ---------------------------------------------------------------------------
// launch
// ---------------------------------------------------------------------------
extern "C" void kernel_launch(void* const* d_in, const int* in_sizes, int n_in,
                              void* d_out, int out_size) {
    const float* x   = (const float*)d_in[0];
    const void*  ei  = d_in[1];
    const float* W1l = (const float*)d_in[2];
    const float* W1r = (const float*)d_in[3];
    const float* b1  = (const float*)d_in[4];
    const float* W2l = (const float*)d_in[5];
    const float* W2r = (const float*)d_in[6];
    const float* b2  = (const float*)d_in[7];
    float* out = (float*)d_out;

    const int n  = in_sizes[0] / 128;   // 100000
    const int nE = in_sizes[1] / 2;     // 1600000

    detect_kernel<<<1, 32>>>((const int*)ei);
    zero_deg_kernel<<<(n / 4 + 255) / 256, 256>>>(n / 4);
    zero_agg_kernel<<<(n * 32 + 255) / 256, 256>>>(n * 32);

    // convert edges (+ fused degree count)
    convert_kernel<<<(nE + 255) / 256, 256>>>(ei, nE, n);
    rdeg_kernel<<<(n + 255) / 256, 256>>>(n);

    // ---- Layer 1: aggregate raw x ----
    {
        long long threads = (long long)nE * 32;
        scatter_kernel<128, false>
            <<<(unsigned)((threads + 255) / 256), 256>>>(x, nE);
    }
    // h = relu([rdeg*agg | x] @ [W1l;W1r] + b1)
    gemm1_kernel<<<(n + 63) / 64, 256>>>(x, W1l, W1r, b1, n);

    // ---- Layer 2 ----
    zero_agg_kernel<<<(n * 16 + 255) / 256, 256>>>(n * 16);
    gemm2_kernel<0><<<(n + 127) / 128, 256>>>(W2l, nullptr, nullptr, n);
    {
        long long threads = (long long)nE * 16;
        scatter_kernel<64, true>
            <<<(unsigned)((threads + 255) / 256), 256>>>(nullptr, nE);
    }
    gemm2_kernel<1><<<(n + 127) / 128, 256>>>(W2r, b2, out, n);
}

// round 10
// speedup vs baseline: 1.7687x; 1.1082x over previous
#include <cuda_runtime.h>
#include <cstddef>

#define NN 100000
#define EE 1600000

// Scratch (device globals, referenced directly from device code)
__device__ float g_deg[NN];                 // degree, then 1/max(deg,1)
__device__ float g_agg[(size_t)NN * 128];
__device__ float g_y[(size_t)NN * 128];
__device__ float g_h[(size_t)NN * 128];
__device__ int2  g_edges[EE];               // clamped (src, dst)
__device__ int   g_is64;

// ---------------------------------------------------------------------------
// tf32 helpers
// ---------------------------------------------------------------------------
__device__ __forceinline__ unsigned f2tf32(float f) {
    unsigned r; asm("cvt.rna.tf32.f32 %0, %1;" : "=r"(r) : "f"(f)); return r;
}
__device__ __forceinline__ void split_tf32(float f, unsigned& hi, unsigned& lo) {
    hi = f2tf32(f);
    lo = f2tf32(f - __uint_as_float(hi));
}
__device__ __forceinline__ void mma_tf32(float4& d, const unsigned a[4],
                                         const unsigned b[2]) {
    asm volatile(
        "mma.sync.aligned.m16n8k8.row.col.f32.tf32.tf32.f32 "
        "{%0,%1,%2,%3}, {%4,%5,%6,%7}, {%8,%9}, {%0,%1,%2,%3};"
        : "+f"(d.x), "+f"(d.y), "+f"(d.z), "+f"(d.w)
        : "r"(a[0]), "r"(a[1]), "r"(a[2]), "r"(a[3]), "r"(b[0]), "r"(b[1]));
}

// ---------------------------------------------------------------------------
// dtype detection (int64 values < 1e5 have zero high words)
// ---------------------------------------------------------------------------
__global__ void detect_kernel(const int* __restrict__ ei32) {
    if (blockIdx.x == 0 && threadIdx.x == 0) {
        int is64 = 1;
        for (int i = 0; i < 64; i++)
            if (ei32[2 * i + 1] != 0) { is64 = 0; break; }
        g_is64 = is64;
    }
}

// ---------------------------------------------------------------------------
// edge conversion -> clamped int2, fused degree count
// ---------------------------------------------------------------------------
__global__ void convert_kernel(const void* __restrict__ ei, int nE, int n) {
    int e = blockIdx.x * blockDim.x + threadIdx.x;
    if (e >= nE) return;
    long long s, d;
    if (g_is64) {
        s = ((const long long*)ei)[e];
        d = ((const long long*)ei)[(size_t)nE + e];
    } else {
        s = ((const int*)ei)[e];
        d = ((const int*)ei)[(size_t)nE + e];
    }
    if (s < 0) s = 0; if (s >= n) s = n - 1;
    if (d < 0) d = 0; if (d >= n) d = n - 1;
    g_edges[e] = make_int2((int)s, (int)d);
    atomicAdd(&g_deg[(int)d], 1.0f);
}

// ---------------------------------------------------------------------------
// zero / rdeg
// ---------------------------------------------------------------------------
__global__ void zero_deg_kernel(int n4) {
    int i = blockIdx.x * blockDim.x + threadIdx.x;
    if (i < n4) ((float4*)g_deg)[i] = make_float4(0.f, 0.f, 0.f, 0.f);
}
__global__ void zero_agg_kernel(int n4) {
    int i = blockIdx.x * blockDim.x + threadIdx.x;
    if (i < n4) ((float4*)g_agg)[i] = make_float4(0.f, 0.f, 0.f, 0.f);
}
__global__ void rdeg_kernel(int n) {
    int i = blockIdx.x * blockDim.x + threadIdx.x;
    if (i < n) g_deg[i] = 1.0f / fmaxf(g_deg[i], 1.0f);
}

// ---------------------------------------------------------------------------
// scatter-add from precomputed edges (red.global.add.v4.f32)
// ---------------------------------------------------------------------------
template <int D, bool USEGY>
__global__ void scatter_kernel(const float* __restrict__ Yarg, int nE) {
    constexpr int LPE = D / 4;                    // 32 or 16
    constexpr int EPW = 32 / LPE;                 // edges per warp
    const int tid = threadIdx.x;
    const int warp = (blockIdx.x * blockDim.x + tid) >> 5;
    const int lane = tid & 31;
    const int sub = lane / LPE;
    const int l = lane % LPE;
    const int e = warp * EPW + sub;
    if (e >= nE) return;
    const float* Y = USEGY ? (const float*)g_y : Yarg;
    int2 ed = g_edges[e];
    float4 v = ((const float4*)(Y + (size_t)ed.x * D))[l];
    float* p = g_agg + (size_t)ed.y * D + l * 4;
    asm volatile("red.global.add.v4.f32 [%0], {%1,%2,%3,%4};"
                 :: "l"(p), "f"(v.x), "f"(v.y), "f"(v.z), "f"(v.w)
                 : "memory");
}

// ---------------------------------------------------------------------------
// GEMM 1 (fused layer 1):  g_h = relu([rdeg*agg | x] @ [W1l ; W1r] + b1)
// tf32 mma m16n8k8 with 3-pass hi/lo compensation (~fp32 accuracy).
// BM=64, BN=128, K=256, KC=32. 8 warps: wm = warp&1 (2x32 M), wn = warp>>1
// (4x32 N). Warp tile 32x32 = 2 m16 x 4 n8 mma tiles.
// ---------------------------------------------------------------------------
__global__ void gemm1_kernel(const float* __restrict__ x,
                             const float* __restrict__ W1l,
                             const float* __restrict__ W1r,
                             const float* __restrict__ b1, int n) {
    constexpr int BM = 64, BN = 128, KC = 32, KCP = 36, BNP = 136;
    __shared__ float sA[BM * KCP];   // 9 KB
    __shared__ float sW[KC * BNP];   // 17 KB
    const int tid = threadIdx.x;
    const int node0 = blockIdx.x * BM;
    const int warp = tid >> 5;
    const int lane = tid & 31;
    const int wm = warp & 1;
    const int wn = warp >> 1;
    const int gid = lane >> 2;       // 0..7
    const int tig = lane & 3;        // 0..3

    float4 acc[2][4];
#pragma unroll
    for (int mt = 0; mt < 2; mt++)
#pragma unroll
        for (int nt = 0; nt < 4; nt++)
            acc[mt][nt] = make_float4(0.f, 0.f, 0.f, 0.f);

    for (int kc = 0; kc < 256; kc += KC) {
        const bool first = kc < 128;
        const int koff = first ? kc : kc - 128;
        const float* Abase = first ? (const float*)g_agg : x;
        const float* Wbase = (first ? W1l : W1r) + (size_t)koff * BN;

        for (int t = tid; t < BM * (KC / 4); t += 256) {
            int m = t >> 3, kq = t & 7;
            int node = node0 + m;
            float4 v = make_float4(0.f, 0.f, 0.f, 0.f);
            if (node < n) {
                v = ((const float4*)(Abase + (size_t)node * 128 + koff))[kq];
                if (first) {
                    float r = g_deg[node];    // rdeg
                    v.x *= r; v.y *= r; v.z *= r; v.w *= r;
                }
            }
            *(float4*)(sA + m * KCP + kq * 4) = v;
        }
        for (int t = tid; t < KC * (BN / 4); t += 256) {
            int k = t / (BN / 4), nq = t % (BN / 4);
            *(float4*)(sW + k * BNP + nq * 4) =
                ((const float4*)(Wbase + (size_t)k * BN))[nq];
        }
        __syncthreads();

#pragma unroll
        for (int k8 = 0; k8 < KC / 8; k8++) {
            const int k0 = k8 * 8;
            unsigned ah[2][4], al[2][4], bh[4][2], bl[4][2];
#pragma unroll
            for (int mt = 0; mt < 2; mt++) {
                int mb = wm * 32 + mt * 16;
                float a0 = sA[(mb + gid) * KCP + k0 + tig];
                float a1 = sA[(mb + gid + 8) * KCP + k0 + tig];
                float a2 = sA[(mb + gid) * KCP + k0 + tig + 4];
                float a3 = sA[(mb + gid + 8) * KCP + k0 + tig + 4];
                split_tf32(a0, ah[mt][0], al[mt][0]);
                split_tf32(a1, ah[mt][1], al[mt][1]);
                split_tf32(a2, ah[mt][2], al[mt][2]);
                split_tf32(a3, ah[mt][3], al[mt][3]);
            }
#pragma unroll
            for (int nt = 0; nt < 4; nt++) {
                int nb = wn * 32 + nt * 8;
                float b0 = sW[(k0 + tig) * BNP + nb + gid];
                float b1v = sW[(k0 + tig + 4) * BNP + nb + gid];
                split_tf32(b0, bh[nt][0], bl[nt][0]);
                split_tf32(b1v, bh[nt][1], bl[nt][1]);
            }
#pragma unroll
            for (int mt = 0; mt < 2; mt++)
#pragma unroll
                for (int nt = 0; nt < 4; nt++) {
                    mma_tf32(acc[mt][nt], ah[mt], bh[nt]);
                    mma_tf32(acc[mt][nt], ah[mt], bl[nt]);
                    mma_tf32(acc[mt][nt], al[mt], bh[nt]);
                }
        }
        __syncthreads();
    }

    // epilogue: + bias, relu, store float2 pairs
#pragma unroll
    for (int mt = 0; mt < 2; mt++) {
        int r0 = node0 + wm * 32 + mt * 16 + gid;
        int r1 = r0 + 8;
#pragma unroll
        for (int nt = 0; nt < 4; nt++) {
            int c = wn * 32 + nt * 8 + tig * 2;
            float bx = b1[c], by = b1[c + 1];
            if (r0 < n) {
                float2 v = make_float2(fmaxf(acc[mt][nt].x + bx, 0.f),
                                       fmaxf(acc[mt][nt].y + by, 0.f));
                *(float2*)(g_h + (size_t)r0 * 128 + c) = v;
            }
            if (r1 < n) {
                float2 v = make_float2(fmaxf(acc[mt][nt].z + bx, 0.f),
                                       fmaxf(acc[mt][nt].w + by, 0.f));
                *(float2*)(g_h + (size_t)r1 * 128 + c) = v;
            }
        }
    }
}

// ---------------------------------------------------------------------------
// GEMM 2/3 (layer 2): C[n,64] = g_h[n,128] @ W[128,64]
// MODE 0: C = g_y.  MODE 1: C = out, adds g_agg*rdeg + b2.
// BM=128, BN=64, KC=32. 8 warps: wm = warp&3 (4x32 M), wn = warp>>2 (2x32 N).
// ---------------------------------------------------------------------------
template <int MODE>
__global__ void gemm2_kernel(const float* __restrict__ W,
                             const float* __restrict__ b2,
                             float* __restrict__ Cout, int n) {
    constexpr int BM = 128, BN = 64, KC = 32, KCP = 36, BNP = 72;
    __shared__ float sA[BM * KCP];   // 18 KB
    __shared__ float sW[KC * BNP];   // 9 KB
    const int tid = threadIdx.x;
    const int node0 = blockIdx.x * BM;
    const int warp = tid >> 5;
    const int lane = tid & 31;
    const int wm = warp & 3;
    const int wn = warp >> 2;
    const int gid = lane >> 2;
    const int tig = lane & 3;

    float4 acc[2][4];
#pragma unroll
    for (int mt = 0; mt < 2; mt++)
#pragma unroll
        for (int nt = 0; nt < 4; nt++)
            acc[mt][nt] = make_float4(0.f, 0.f, 0.f, 0.f);

    for (int kc = 0; kc < 128; kc += KC) {
        for (int t = tid; t < BM * (KC / 4); t += 256) {
            int m = t >> 3, kq = t & 7;
            int node = node0 + m;
            float4 v = make_float4(0.f, 0.f, 0.f, 0.f);
            if (node < n)
                v = ((const float4*)(g_h + (size_t)node * 128 + kc))[kq];
            *(float4*)(sA + m * KCP + kq * 4) = v;
        }
        for (int t = tid; t < KC * (BN / 4); t += 256) {
            int k = t / (BN / 4), nq = t % (BN / 4);
            *(float4*)(sW + k * BNP + nq * 4) =
                ((const float4*)(W + (size_t)(kc + k) * BN))[nq];
        }
        __syncthreads();

#pragma unroll
        for (int k8 = 0; k8 < KC / 8; k8++) {
            const int k0 = k8 * 8;
            unsigned ah[2][4], al[2][4], bh[4][2], bl[4][2];
#pragma unroll
            for (int mt = 0; mt < 2; mt++) {
                int mb = wm * 32 + mt * 16;
                float a0 = sA[(mb + gid) * KCP + k0 + tig];
                float a1 = sA[(mb + gid + 8) * KCP + k0 + tig];
                float a2 = sA[(mb + gid) * KCP + k0 + tig + 4];
                float a3 = sA[(mb + gid + 8) * KCP + k0 + tig + 4];
                split_tf32(a0, ah[mt][0], al[mt][0]);
                split_tf32(a1, ah[mt][1], al[mt][1]);
                split_tf32(a2, ah[mt][2], al[mt][2]);
                split_tf32(a3, ah[mt][3], al[mt][3]);
            }
#pragma unroll
            for (int nt = 0; nt < 4; nt++) {
                int nb = wn * 32 + nt * 8;
                float b0 = sW[(k0 + tig) * BNP + nb + gid];
                float b1v = sW[(k0 + tig + 4) * BNP + nb + gid];
                split_tf32(b0, bh[nt][0], bl[nt][0]);
                split_tf32(b1v, bh[nt][1], bl[nt][1]);
            }
#pragma unroll
            for (int mt = 0; mt < 2; mt++)
#pragma unroll
                for (int nt = 0; nt < 4; nt++) {
                    mma_tf32(acc[mt][nt], ah[mt], bh[nt]);
                    mma_tf32(acc[mt][nt], ah[mt], bl[nt]);
                    mma_tf32(acc[mt][nt], al[mt], bh[nt]);
                }
        }
        __syncthreads();
    }

    float* C = (MODE == 0) ? (float*)g_y : Cout;
#pragma unroll
    for (int mt = 0; mt < 2; mt++) {
        int r0 = node0 + wm * 32 + mt * 16 + gid;
#pragma unroll
        for (int nt = 0; nt < 4; nt++) {
            int c = wn * 32 + nt * 8 + tig * 2;
#pragma unroll
            for (int half = 0; half < 2; half++) {
                int r = r0 + half * 8;
                if (r >= n) continue;
                float vx = half ? acc[mt][nt].z : acc[mt][nt].x;
                float vy = half ? acc[mt][nt].w : acc[mt][nt].y;
                if (MODE == 1) {
                    float rd = g_deg[r];
                    float2 ag = *(const float2*)(g_agg + (size_t)r * 64 + c);
                    vx += ag.x * rd + b2[c];
                    vy += ag.y * rd + b2[c + 1];
                }
                *(float2*)(C + (size_t)r * 64 + c) = make_float2(vx, vy);
            }
        }
    }
}

// ---------------------------------------------------------------------------
// launch
// ---------------------------------------------------------------------------
extern "C" void kernel_launch(void* const* d_in, const int* in_sizes, int n_in,
                              void* d_out, int out_size) {
    const float* x   = (const float*)d_in[0];
    const void*  ei  = d_in[1];
    const float* W1l = (const float*)d_in[2];
    const float* W1r = (const float*)d_in[3];
    const float* b1  = (const float*)d_in[4];
    const float* W2l = (const float*)d_in[5];
    const float* W2r = (const float*)d_in[6];
    const float* b2  = (const float*)d_in[7];
    float* out = (float*)d_out;

    const int n  = in_sizes[0] / 128;   // 100000
    const int nE = in_sizes[1] / 2;     // 1600000

    detect_kernel<<<1, 32>>>((const int*)ei);
    zero_deg_kernel<<<(n / 4 + 255) / 256, 256>>>(n / 4);
    zero_agg_kernel<<<(n * 32 + 255) / 256, 256>>>(n * 32);

    convert_kernel<<<(nE + 255) / 256, 256>>>(ei, nE, n);
    rdeg_kernel<<<(n + 255) / 256, 256>>>(n);

    // ---- Layer 1: aggregate raw x ----
    {
        long long threads = (long long)nE * 32;
        scatter_kernel<128, false>
            <<<(unsigned)((threads + 255) / 256), 256>>>(x, nE);
    }
    gemm1_kernel<<<(n + 63) / 64, 256>>>(x, W1l, W1r, b1, n);

    // ---- Layer 2 ----
    zero_agg_kernel<<<(n * 16 + 255) / 256, 256>>>(n * 16);
    gemm2_kernel<0><<<(n + 127) / 128, 256>>>(W2l, nullptr, nullptr, n);
    {
        long long threads = (long long)nE * 16;
        scatter_kernel<64, true>
            <<<(unsigned)((threads + 255) / 256), 256>>>(nullptr, nE);
    }
    gemm2_kernel<1><<<(n + 127) / 128, 256>>>(W2r, b2, out, n);
}

// round 11
// speedup vs baseline: 1.8248x; 1.0317x over previous
#include <cuda_runtime.h>
#include <cuda_bf16.h>
#include <cstddef>

#define NN 100000
#define EE 1600000

// Scratch (device globals, referenced directly from device code)
__device__ float g_deg[NN];                 // raw degree
__device__ float g_agg[(size_t)NN * 128];
__device__ float g_y[(size_t)NN * 128];
__device__ float g_h[(size_t)NN * 128];
__device__ int2  g_edges[EE];               // clamped (src, dst)
__device__ int   g_is64;

// ---------------------------------------------------------------------------
// bf16 split + mma helpers
// ---------------------------------------------------------------------------
__device__ __forceinline__ void split2(float2 v, unsigned& hi, unsigned& lo) {
    __nv_bfloat162 h = __float22bfloat162_rn(v);
    float2 hf = __bfloat1622float2(h);
    __nv_bfloat162 l = __float22bfloat162_rn(make_float2(v.x - hf.x, v.y - hf.y));
    hi = *reinterpret_cast<unsigned*>(&h);
    lo = *reinterpret_cast<unsigned*>(&l);
}
__device__ __forceinline__ void mma_bf16(float4& d, const unsigned a[4],
                                         const unsigned b[2]) {
    asm volatile(
        "mma.sync.aligned.m16n8k16.row.col.f32.bf16.bf16.f32 "
        "{%0,%1,%2,%3}, {%4,%5,%6,%7}, {%8,%9}, {%0,%1,%2,%3};"
        : "+f"(d.x), "+f"(d.y), "+f"(d.z), "+f"(d.w)
        : "r"(a[0]), "r"(a[1]), "r"(a[2]), "r"(a[3]), "r"(b[0]), "r"(b[1]));
}

// ---------------------------------------------------------------------------
// dtype detection (int64 values < 1e5 have zero high words)
// ---------------------------------------------------------------------------
__global__ void detect_kernel(const int* __restrict__ ei32) {
    if (blockIdx.x == 0 && threadIdx.x == 0) {
        int is64 = 1;
        for (int i = 0; i < 64; i++)
            if (ei32[2 * i + 1] != 0) { is64 = 0; break; }
        g_is64 = is64;
    }
}

// ---------------------------------------------------------------------------
// zero deg + agg(128 cols) in one launch
// ---------------------------------------------------------------------------
__global__ void zero_all_kernel(int ndeg4, int nagg4) {
    int i = blockIdx.x * blockDim.x + threadIdx.x;
    float4 z = make_float4(0.f, 0.f, 0.f, 0.f);
    if (i < ndeg4) ((float4*)g_deg)[i] = z;
    else if (i < ndeg4 + nagg4) ((float4*)g_agg)[i - ndeg4] = z;
}
__global__ void zero_agg_kernel(int n4) {
    int i = blockIdx.x * blockDim.x + threadIdx.x;
    if (i < n4) ((float4*)g_agg)[i] = make_float4(0.f, 0.f, 0.f, 0.f);
}

// ---------------------------------------------------------------------------
// edge conversion -> clamped int2, fused degree count
// ---------------------------------------------------------------------------
__global__ void convert_kernel(const void* __restrict__ ei, int nE, int n) {
    int e = blockIdx.x * blockDim.x + threadIdx.x;
    if (e >= nE) return;
    long long s, d;
    if (g_is64) {
        s = ((const long long*)ei)[e];
        d = ((const long long*)ei)[(size_t)nE + e];
    } else {
        s = ((const int*)ei)[e];
        d = ((const int*)ei)[(size_t)nE + e];
    }
    if (s < 0) s = 0; if (s >= n) s = n - 1;
    if (d < 0) d = 0; if (d >= n) d = n - 1;
    g_edges[e] = make_int2((int)s, (int)d);
    atomicAdd(&g_deg[(int)d], 1.0f);
}

// ---------------------------------------------------------------------------
// scatter-add from precomputed edges (red.global.add.v4.f32)
// ---------------------------------------------------------------------------
template <int D, bool USEGY>
__global__ void scatter_kernel(const float* __restrict__ Yarg, int nE) {
    constexpr int LPE = D / 4;                    // 32 or 16
    constexpr int EPW = 32 / LPE;
    const int tid = threadIdx.x;
    const int warp = (blockIdx.x * blockDim.x + tid) >> 5;
    const int lane = tid & 31;
    const int sub = lane / LPE;
    const int l = lane % LPE;
    const int e = warp * EPW + sub;
    if (e >= nE) return;
    const float* Y = USEGY ? (const float*)g_y : Yarg;
    int2 ed = g_edges[e];
    float4 v = ((const float4*)(Y + (size_t)ed.x * D))[l];
    float* p = g_agg + (size_t)ed.y * D + l * 4;
    asm volatile("red.global.add.v4.f32 [%0], {%1,%2,%3,%4};"
                 :: "l"(p), "f"(v.x), "f"(v.y), "f"(v.z), "f"(v.w)
                 : "memory");
}

// ---------------------------------------------------------------------------
// GEMM 1 (fused layer 1):  g_h = relu([agg/deg | x] @ [W1l ; W1r] + b1)
// bf16 2-split 3-pass mma m16n8k16 (error ~2^-18 per product).
// Operands pre-split into hi/lo bf16x2 smem at staging.
// BM=64, BN=128, K=256, KC=32. 8 warps: wm=warp&1, wn=warp>>1; warp tile 32x32.
// smem u32 layout [row][k/2] with stride KHP=20 (conflict-free fragments).
// ---------------------------------------------------------------------------
__global__ void gemm1_kernel(const float* __restrict__ x,
                             const float* __restrict__ W1l,
                             const float* __restrict__ W1r,
                             const float* __restrict__ b1, int n) {
    constexpr int BM = 64, BN = 128, KC = 32, KHP = 20;
    __shared__ unsigned sAh[BM * KHP], sAl[BM * KHP];   // 5 KB each
    __shared__ unsigned sWh[BN * KHP], sWl[BN * KHP];   // 10 KB each
    const int tid = threadIdx.x;
    const int node0 = blockIdx.x * BM;
    const int warp = tid >> 5;
    const int lane = tid & 31;
    const int wm = warp & 1;
    const int wn = warp >> 1;
    const int gid = lane >> 2;
    const int tig = lane & 3;

    float4 acc[2][4];
#pragma unroll
    for (int mt = 0; mt < 2; mt++)
#pragma unroll
        for (int nt = 0; nt < 4; nt++)
            acc[mt][nt] = make_float4(0.f, 0.f, 0.f, 0.f);

    for (int kc = 0; kc < 256; kc += KC) {
        const bool first = kc < 128;
        const int koff = first ? kc : kc - 128;
        const float* Abase = first ? (const float*)g_agg : x;
        const float* Wbase = (first ? W1l : W1r) + (size_t)koff * BN;

        // stage A (split to bf16 hi/lo); first half scaled by 1/max(deg,1)
        for (int t = tid; t < BM * (KC / 4); t += 256) {
            int m = t >> 3, kq = t & 7;
            int node = node0 + m;
            float4 v = make_float4(0.f, 0.f, 0.f, 0.f);
            if (node < n) {
                v = ((const float4*)(Abase + (size_t)node * 128 + koff))[kq];
                if (first) {
                    float r = 1.0f / fmaxf(g_deg[node], 1.0f);
                    v.x *= r; v.y *= r; v.z *= r; v.w *= r;
                }
            }
            unsigned h0, l0, h1, l1;
            split2(make_float2(v.x, v.y), h0, l0);
            split2(make_float2(v.z, v.w), h1, l1);
            sAh[m * KHP + 2 * kq]     = h0;
            sAl[m * KHP + 2 * kq]     = l0;
            sAh[m * KHP + 2 * kq + 1] = h1;
            sAl[m * KHP + 2 * kq + 1] = l1;
        }
        // stage W transposed-pairs: u32 [n][k/2] packs (W[k][n], W[k+1][n])
        for (int t = tid; t < (KC / 2) * (BN / 4); t += 256) {
            int k2 = t >> 5;        // 0..15
            int nq = t & 31;        // 0..31
            const float* base = Wbase + (size_t)(2 * k2) * BN + nq * 4;
            float4 va = *(const float4*)base;
            float4 vb = *(const float4*)(base + BN);
            float av[4] = {va.x, va.y, va.z, va.w};
            float bv[4] = {vb.x, vb.y, vb.z, vb.w};
#pragma unroll
            for (int i = 0; i < 4; i++) {
                unsigned h, l;
                split2(make_float2(av[i], bv[i]), h, l);
                sWh[(nq * 4 + i) * KHP + k2] = h;
                sWl[(nq * 4 + i) * KHP + k2] = l;
            }
        }
        __syncthreads();

#pragma unroll
        for (int k16 = 0; k16 < 2; k16++) {
            const int kh = k16 * 8;
            unsigned ah[2][4], al[2][4], bh[4][2], bl[4][2];
#pragma unroll
            for (int mt = 0; mt < 2; mt++) {
                int r0 = (wm * 32 + mt * 16 + gid) * KHP;
                int r1 = r0 + 8 * KHP;
                ah[mt][0] = sAh[r0 + kh + tig];
                ah[mt][1] = sAh[r1 + kh + tig];
                ah[mt][2] = sAh[r0 + kh + tig + 4];
                ah[mt][3] = sAh[r1 + kh + tig + 4];
                al[mt][0] = sAl[r0 + kh + tig];
                al[mt][1] = sAl[r1 + kh + tig];
                al[mt][2] = sAl[r0 + kh + tig + 4];
                al[mt][3] = sAl[r1 + kh + tig + 4];
            }
#pragma unroll
            for (int nt = 0; nt < 4; nt++) {
                int rn = (wn * 32 + nt * 8 + gid) * KHP;
                bh[nt][0] = sWh[rn + kh + tig];
                bh[nt][1] = sWh[rn + kh + tig + 4];
                bl[nt][0] = sWl[rn + kh + tig];
                bl[nt][1] = sWl[rn + kh + tig + 4];
            }
#pragma unroll
            for (int mt = 0; mt < 2; mt++)
#pragma unroll
                for (int nt = 0; nt < 4; nt++) {
                    mma_bf16(acc[mt][nt], ah[mt], bh[nt]);
                    mma_bf16(acc[mt][nt], ah[mt], bl[nt]);
                    mma_bf16(acc[mt][nt], al[mt], bh[nt]);
                }
        }
        __syncthreads();
    }

    // epilogue: + bias, relu
#pragma unroll
    for (int mt = 0; mt < 2; mt++) {
        int r0 = node0 + wm * 32 + mt * 16 + gid;
        int r1 = r0 + 8;
#pragma unroll
        for (int nt = 0; nt < 4; nt++) {
            int c = wn * 32 + nt * 8 + tig * 2;
            float bx = b1[c], by = b1[c + 1];
            if (r0 < n) {
                float2 v = make_float2(fmaxf(acc[mt][nt].x + bx, 0.f),
                                       fmaxf(acc[mt][nt].y + by, 0.f));
                *(float2*)(g_h + (size_t)r0 * 128 + c) = v;
            }
            if (r1 < n) {
                float2 v = make_float2(fmaxf(acc[mt][nt].z + bx, 0.f),
                                       fmaxf(acc[mt][nt].w + by, 0.f));
                *(float2*)(g_h + (size_t)r1 * 128 + c) = v;
            }
        }
    }
}

// ---------------------------------------------------------------------------
// GEMM 2/3 (layer 2): C[n,64] = g_h[n,128] @ W[128,64]
// MODE 0: C = g_y.  MODE 1: C = out, adds g_agg/deg + b2.
// BM=128, BN=64, KC=32. wm=warp&3, wn=warp>>2.
// ---------------------------------------------------------------------------
template <int MODE>
__global__ void gemm2_kernel(const float* __restrict__ W,
                             const float* __restrict__ b2,
                             float* __restrict__ Cout, int n) {
    constexpr int BM = 128, BN = 64, KC = 32, KHP = 20;
    __shared__ unsigned sAh[BM * KHP], sAl[BM * KHP];   // 10 KB each
    __shared__ unsigned sWh[BN * KHP], sWl[BN * KHP];   // 5 KB each
    const int tid = threadIdx.x;
    const int node0 = blockIdx.x * BM;
    const int warp = tid >> 5;
    const int lane = tid & 31;
    const int wm = warp & 3;
    const int wn = warp >> 2;
    const int gid = lane >> 2;
    const int tig = lane & 3;

    float4 acc[2][4];
#pragma unroll
    for (int mt = 0; mt < 2; mt++)
#pragma unroll
        for (int nt = 0; nt < 4; nt++)
            acc[mt][nt] = make_float4(0.f, 0.f, 0.f, 0.f);

    for (int kc = 0; kc < 128; kc += KC) {
        for (int t = tid; t < BM * (KC / 4); t += 256) {
            int m = t >> 3, kq = t & 7;
            int node = node0 + m;
            float4 v = make_float4(0.f, 0.f, 0.f, 0.f);
            if (node < n)
                v = ((const float4*)(g_h + (size_t)node * 128 + kc))[kq];
            unsigned h0, l0, h1, l1;
            split2(make_float2(v.x, v.y), h0, l0);
            split2(make_float2(v.z, v.w), h1, l1);
            sAh[m * KHP + 2 * kq]     = h0;
            sAl[m * KHP + 2 * kq]     = l0;
            sAh[m * KHP + 2 * kq + 1] = h1;
            sAl[m * KHP + 2 * kq + 1] = l1;
        }
        for (int t = tid; t < (KC / 2) * (BN / 4); t += 256) {
            int k2 = t >> 4;        // 0..15
            int nq = t & 15;        // 0..15
            const float* base = W + (size_t)(kc + 2 * k2) * BN + nq * 4;
            float4 va = *(const float4*)base;
            float4 vb = *(const float4*)(base + BN);
            float av[4] = {va.x, va.y, va.z, va.w};
            float bv[4] = {vb.x, vb.y, vb.z, vb.w};
#pragma unroll
            for (int i = 0; i < 4; i++) {
                unsigned h, l;
                split2(make_float2(av[i], bv[i]), h, l);
                sWh[(nq * 4 + i) * KHP + k2] = h;
                sWl[(nq * 4 + i) * KHP + k2] = l;
            }
        }
        __syncthreads();

#pragma unroll
        for (int k16 = 0; k16 < 2; k16++) {
            const int kh = k16 * 8;
            unsigned ah[2][4], al[2][4], bh[4][2], bl[4][2];
#pragma unroll
            for (int mt = 0; mt < 2; mt++) {
                int r0 = (wm * 32 + mt * 16 + gid) * KHP;
                int r1 = r0 + 8 * KHP;
                ah[mt][0] = sAh[r0 + kh + tig];
                ah[mt][1] = sAh[r1 + kh + tig];
                ah[mt][2] = sAh[r0 + kh + tig + 4];
                ah[mt][3] = sAh[r1 + kh + tig + 4];
                al[mt][0] = sAl[r0 + kh + tig];
                al[mt][1] = sAl[r1 + kh + tig];
                al[mt][2] = sAl[r0 + kh + tig + 4];
                al[mt][3] = sAl[r1 + kh + tig + 4];
            }
#pragma unroll
            for (int nt = 0; nt < 4; nt++) {
                int rn = (wn * 32 + nt * 8 + gid) * KHP;
                bh[nt][0] = sWh[rn + kh + tig];
                bh[nt][1] = sWh[rn + kh + tig + 4];
                bl[nt][0] = sWl[rn + kh + tig];
                bl[nt][1] = sWl[rn + kh + tig + 4];
            }
#pragma unroll
            for (int mt = 0; mt < 2; mt++)
#pragma unroll
                for (int nt = 0; nt < 4; nt++) {
                    mma_bf16(acc[mt][nt], ah[mt], bh[nt]);
                    mma_bf16(acc[mt][nt], ah[mt], bl[nt]);
                    mma_bf16(acc[mt][nt], al[mt], bh[nt]);
                }
        }
        __syncthreads();
    }

    float* C = (MODE == 0) ? (float*)g_y : Cout;
#pragma unroll
    for (int mt = 0; mt < 2; mt++) {
        int r0 = node0 + wm * 32 + mt * 16 + gid;
#pragma unroll
        for (int nt = 0; nt < 4; nt++) {
            int c = wn * 32 + nt * 8 + tig * 2;
#pragma unroll
            for (int half = 0; half < 2; half++) {
                int r = r0 + half * 8;
                if (r >= n) continue;
                float vx = half ? acc[mt][nt].z : acc[mt][nt].x;
                float vy = half ? acc[mt][nt].w : acc[mt][nt].y;
                if (MODE == 1) {
                    float rd = 1.0f / fmaxf(g_deg[r], 1.0f);
                    float2 ag = *(const float2*)(g_agg + (size_t)r * 64 + c);
                    vx += ag.x * rd + b2[c];
                    vy += ag.y * rd + b2[c + 1];
                }
                *(float2*)(C + (size_t)r * 64 + c) = make_float2(vx, vy);
            }
        }
    }
}

// ---------------------------------------------------------------------------
// launch
// ---------------------------------------------------------------------------
extern "C" void kernel_launch(void* const* d_in, const int* in_sizes, int n_in,
                              void* d_out, int out_size) {
    const float* x   = (const float*)d_in[0];
    const void*  ei  = d_in[1];
    const float* W1l = (const float*)d_in[2];
    const float* W1r = (const float*)d_in[3];
    const float* b1  = (const float*)d_in[4];
    const float* W2l = (const float*)d_in[5];
    const float* W2r = (const float*)d_in[6];
    const float* b2  = (const float*)d_in[7];
    float* out = (float*)d_out;

    const int n  = in_sizes[0] / 128;   // 100000
    const int nE = in_sizes[1] / 2;     // 1600000

    detect_kernel<<<1, 32>>>((const int*)ei);
    {
        int ndeg4 = n / 4, nagg4 = n * 32;
        zero_all_kernel<<<(ndeg4 + nagg4 + 255) / 256, 256>>>(ndeg4, nagg4);
    }
    convert_kernel<<<(nE + 255) / 256, 256>>>(ei, nE, n);

    // ---- Layer 1 ----
    {
        long long threads = (long long)nE * 32;
        scatter_kernel<128, false>
            <<<(unsigned)((threads + 255) / 256), 256>>>(x, nE);
    }
    gemm1_kernel<<<(n + 63) / 64, 256>>>(x, W1l, W1r, b1, n);

    // ---- Layer 2 ----
    zero_agg_kernel<<<(n * 16 + 255) / 256, 256>>>(n * 16);
    gemm2_kernel<0><<<(n + 127) / 128, 256>>>(W2l, nullptr, nullptr, n);
    {
        long long threads = (long long)nE * 16;
        scatter_kernel<64, true>
            <<<(unsigned)((threads + 255) / 256), 256>>>(nullptr, nE);
    }
    gemm2_kernel<1><<<(n + 127) / 128, 256>>>(W2r, b2, out, n);
}

// round 12
// speedup vs baseline: 2.6702x; 1.4633x over previous
#include <cuda_runtime.h>
#include <cuda_bf16.h>
#include <cstddef>

#define NN 100000
#define EE 1600000

// Scratch (device globals, referenced directly from device code)
__device__ int   g_degi[NN];
__device__ int   g_off[NN + 1];
__device__ int   g_cur[NN];
__device__ int   g_offL[NN];
__device__ int   g_part[128];
__device__ int   g_srcs[EE];                // dst-binned source indices
__device__ int2  g_edges[EE];               // clamped (src, dst)
__device__ float g_agg[(size_t)NN * 128];   // mean-aggregated features
__device__ float g_y[(size_t)NN * 128];
__device__ float g_h[(size_t)NN * 128];
__device__ int   g_is64;

// ---------------------------------------------------------------------------
// bf16 split + mma helpers
// ---------------------------------------------------------------------------
__device__ __forceinline__ void split2(float2 v, unsigned& hi, unsigned& lo) {
    __nv_bfloat162 h = __float22bfloat162_rn(v);
    float2 hf = __bfloat1622float2(h);
    __nv_bfloat162 l = __float22bfloat162_rn(make_float2(v.x - hf.x, v.y - hf.y));
    hi = *reinterpret_cast<unsigned*>(&h);
    lo = *reinterpret_cast<unsigned*>(&l);
}
__device__ __forceinline__ void mma_bf16(float4& d, const unsigned a[4],
                                         const unsigned b[2]) {
    asm volatile(
        "mma.sync.aligned.m16n8k16.row.col.f32.bf16.bf16.f32 "
        "{%0,%1,%2,%3}, {%4,%5,%6,%7}, {%8,%9}, {%0,%1,%2,%3};"
        : "+f"(d.x), "+f"(d.y), "+f"(d.z), "+f"(d.w)
        : "r"(a[0]), "r"(a[1]), "r"(a[2]), "r"(a[3]), "r"(b[0]), "r"(b[1]));
}

// ---------------------------------------------------------------------------
// dtype detection (int64 values < 1e5 have zero high words)
// ---------------------------------------------------------------------------
__global__ void detect_kernel(const int* __restrict__ ei32) {
    if (blockIdx.x == 0 && threadIdx.x == 0) {
        int is64 = 1;
        for (int i = 0; i < 64; i++)
            if (ei32[2 * i + 1] != 0) { is64 = 0; break; }
        g_is64 = is64;
    }
}

__global__ void zero_degi_kernel(int n) {
    int i = blockIdx.x * blockDim.x + threadIdx.x;
    if (i < n) g_degi[i] = 0;
}

// ---------------------------------------------------------------------------
// edge conversion -> clamped int2, fused int degree count
// ---------------------------------------------------------------------------
__global__ void convert_kernel(const void* __restrict__ ei, int nE, int n) {
    int e = blockIdx.x * blockDim.x + threadIdx.x;
    if (e >= nE) return;
    long long s, d;
    if (g_is64) {
        s = ((const long long*)ei)[e];
        d = ((const long long*)ei)[(size_t)nE + e];
    } else {
        s = ((const int*)ei)[e];
        d = ((const int*)ei)[(size_t)nE + e];
    }
    if (s < 0) s = 0; if (s >= n) s = n - 1;
    if (d < 0) d = 0; if (d >= n) d = n - 1;
    g_edges[e] = make_int2((int)s, (int)d);
    atomicAdd(&g_degi[(int)d], 1);
}

// ---------------------------------------------------------------------------
// 3-phase exclusive prefix scan of g_degi -> g_off (chunk = 1024)
// ---------------------------------------------------------------------------
__global__ void scan1_kernel(int n) {
    __shared__ int s[1024];
    const int tid = threadIdx.x;
    const int i = blockIdx.x * 1024 + tid;
    int v = (i < n) ? g_degi[i] : 0;
    s[tid] = v;
    __syncthreads();
#pragma unroll
    for (int d = 1; d < 1024; d <<= 1) {
        int t = (tid >= d) ? s[tid - d] : 0;
        __syncthreads();
        s[tid] += t;
        __syncthreads();
    }
    if (i < n) g_offL[i] = s[tid] - v;     // exclusive within chunk
    if (tid == 1023) g_part[blockIdx.x] = s[1023];
}
__global__ void scan2_kernel(int nb) {
    if (threadIdx.x == 0 && blockIdx.x == 0) {
        int acc = 0;
        for (int b = 0; b < nb; b++) { int t = g_part[b]; g_part[b] = acc; acc += t; }
    }
}
__global__ void scan3_kernel(int n, int nE) {
    int i = blockIdx.x * blockDim.x + threadIdx.x;
    if (i < n) {
        int off = g_offL[i] + g_part[i >> 10];
        g_off[i] = off;
        g_cur[i] = off;
    }
    if (i == 0) g_off[n] = nE;
}

// ---------------------------------------------------------------------------
// bin edges by dst: g_srcs[g_off[dst] ...] = src
// ---------------------------------------------------------------------------
__global__ void bin_kernel(int nE) {
    int e = blockIdx.x * blockDim.x + threadIdx.x;
    if (e >= nE) return;
    int2 ed = g_edges[e];
    int pos = atomicAdd(&g_cur[ed.y], 1);
    g_srcs[pos] = ed.x;
}

// ---------------------------------------------------------------------------
// CSR mean aggregation: one warp per dst node, no atomics.
// D=128: float4 per lane; D=64: float2 per lane. Stores MEAN into g_agg.
// ---------------------------------------------------------------------------
template <int D, bool USEGY>
__global__ void gather_agg_kernel(const float* __restrict__ Xarg, int n) {
    const int gw = (blockIdx.x * blockDim.x + threadIdx.x) >> 5;
    if (gw >= n) return;
    const int lane = threadIdx.x & 31;
    const float* X = USEGY ? (const float*)g_y : Xarg;
    const int beg = g_off[gw], end = g_off[gw + 1];

    if (D == 128) {
        float4 acc = make_float4(0.f, 0.f, 0.f, 0.f);
        int j = beg;
        for (; j + 4 <= end; j += 4) {
            int s0 = g_srcs[j], s1 = g_srcs[j + 1];
            int s2 = g_srcs[j + 2], s3 = g_srcs[j + 3];
            float4 v0 = ((const float4*)(X + (size_t)s0 * 128))[lane];
            float4 v1 = ((const float4*)(X + (size_t)s1 * 128))[lane];
            float4 v2 = ((const float4*)(X + (size_t)s2 * 128))[lane];
            float4 v3 = ((const float4*)(X + (size_t)s3 * 128))[lane];
            acc.x += (v0.x + v1.x) + (v2.x + v3.x);
            acc.y += (v0.y + v1.y) + (v2.y + v3.y);
            acc.z += (v0.z + v1.z) + (v2.z + v3.z);
            acc.w += (v0.w + v1.w) + (v2.w + v3.w);
        }
        for (; j < end; j++) {
            float4 v = ((const float4*)(X + (size_t)g_srcs[j] * 128))[lane];
            acc.x += v.x; acc.y += v.y; acc.z += v.z; acc.w += v.w;
        }
        float r = 1.0f / (float)max(end - beg, 1);
        acc.x *= r; acc.y *= r; acc.z *= r; acc.w *= r;
        ((float4*)(g_agg + (size_t)gw * 128))[lane] = acc;
    } else {
        float2 acc = make_float2(0.f, 0.f);
        int j = beg;
        for (; j + 4 <= end; j += 4) {
            int s0 = g_srcs[j], s1 = g_srcs[j + 1];
            int s2 = g_srcs[j + 2], s3 = g_srcs[j + 3];
            float2 v0 = ((const float2*)(X + (size_t)s0 * 64))[lane];
            float2 v1 = ((const float2*)(X + (size_t)s1 * 64))[lane];
            float2 v2 = ((const float2*)(X + (size_t)s2 * 64))[lane];
            float2 v3 = ((const float2*)(X + (size_t)s3 * 64))[lane];
            acc.x += (v0.x + v1.x) + (v2.x + v3.x);
            acc.y += (v0.y + v1.y) + (v2.y + v3.y);
        }
        for (; j < end; j++) {
            float2 v = ((const float2*)(X + (size_t)g_srcs[j] * 64))[lane];
            acc.x += v.x; acc.y += v.y;
        }
        float r = 1.0f / (float)max(end - beg, 1);
        acc.x *= r; acc.y *= r;
        ((float2*)(g_agg + (size_t)gw * 64))[lane] = acc;
    }
}

// ---------------------------------------------------------------------------
// GEMM 1 (fused layer 1):  g_h = relu([agg | x] @ [W1l ; W1r] + b1)
// bf16 2-split 3-pass mma m16n8k16. agg already holds the MEAN.
// BM=64, BN=128, K=256, KC=32; smem stride KHP=20 (conflict-free fragments).
// ---------------------------------------------------------------------------
__global__ void gemm1_kernel(const float* __restrict__ x,
                             const float* __restrict__ W1l,
                             const float* __restrict__ W1r,
                             const float* __restrict__ b1, int n) {
    constexpr int BM = 64, BN = 128, KC = 32, KHP = 20;
    __shared__ unsigned sAh[BM * KHP], sAl[BM * KHP];
    __shared__ unsigned sWh[BN * KHP], sWl[BN * KHP];
    const int tid = threadIdx.x;
    const int node0 = blockIdx.x * BM;
    const int warp = tid >> 5;
    const int lane = tid & 31;
    const int wm = warp & 1;
    const int wn = warp >> 1;
    const int gid = lane >> 2;
    const int tig = lane & 3;

    float4 acc[2][4];
#pragma unroll
    for (int mt = 0; mt < 2; mt++)
#pragma unroll
        for (int nt = 0; nt < 4; nt++)
            acc[mt][nt] = make_float4(0.f, 0.f, 0.f, 0.f);

    for (int kc = 0; kc < 256; kc += KC) {
        const bool first = kc < 128;
        const int koff = first ? kc : kc - 128;
        const float* Abase = first ? (const float*)g_agg : x;
        const float* Wbase = (first ? W1l : W1r) + (size_t)koff * BN;

        for (int t = tid; t < BM * (KC / 4); t += 256) {
            int m = t >> 3, kq = t & 7;
            int node = node0 + m;
            float4 v = make_float4(0.f, 0.f, 0.f, 0.f);
            if (node < n)
                v = ((const float4*)(Abase + (size_t)node * 128 + koff))[kq];
            unsigned h0, l0, h1, l1;
            split2(make_float2(v.x, v.y), h0, l0);
            split2(make_float2(v.z, v.w), h1, l1);
            sAh[m * KHP + 2 * kq]     = h0;
            sAl[m * KHP + 2 * kq]     = l0;
            sAh[m * KHP + 2 * kq + 1] = h1;
            sAl[m * KHP + 2 * kq + 1] = l1;
        }
        for (int t = tid; t < (KC / 2) * (BN / 4); t += 256) {
            int k2 = t >> 5;
            int nq = t & 31;
            const float* base = Wbase + (size_t)(2 * k2) * BN + nq * 4;
            float4 va = *(const float4*)base;
            float4 vb = *(const float4*)(base + BN);
            float av[4] = {va.x, va.y, va.z, va.w};
            float bv[4] = {vb.x, vb.y, vb.z, vb.w};
#pragma unroll
            for (int i = 0; i < 4; i++) {
                unsigned h, l;
                split2(make_float2(av[i], bv[i]), h, l);
                sWh[(nq * 4 + i) * KHP + k2] = h;
                sWl[(nq * 4 + i) * KHP + k2] = l;
            }
        }
        __syncthreads();

#pragma unroll
        for (int k16 = 0; k16 < 2; k16++) {
            const int kh = k16 * 8;
            unsigned ah[2][4], al[2][4], bh[4][2], bl[4][2];
#pragma unroll
            for (int mt = 0; mt < 2; mt++) {
                int r0 = (wm * 32 + mt * 16 + gid) * KHP;
                int r1 = r0 + 8 * KHP;
                ah[mt][0] = sAh[r0 + kh + tig];
                ah[mt][1] = sAh[r1 + kh + tig];
                ah[mt][2] = sAh[r0 + kh + tig + 4];
                ah[mt][3] = sAh[r1 + kh + tig + 4];
                al[mt][0] = sAl[r0 + kh + tig];
                al[mt][1] = sAl[r1 + kh + tig];
                al[mt][2] = sAl[r0 + kh + tig + 4];
                al[mt][3] = sAl[r1 + kh + tig + 4];
            }
#pragma unroll
            for (int nt = 0; nt < 4; nt++) {
                int rn = (wn * 32 + nt * 8 + gid) * KHP;
                bh[nt][0] = sWh[rn + kh + tig];
                bh[nt][1] = sWh[rn + kh + tig + 4];
                bl[nt][0] = sWl[rn + kh + tig];
                bl[nt][1] = sWl[rn + kh + tig + 4];
            }
#pragma unroll
            for (int mt = 0; mt < 2; mt++)
#pragma unroll
                for (int nt = 0; nt < 4; nt++) {
                    mma_bf16(acc[mt][nt], ah[mt], bh[nt]);
                    mma_bf16(acc[mt][nt], ah[mt], bl[nt]);
                    mma_bf16(acc[mt][nt], al[mt], bh[nt]);
                }
        }
        __syncthreads();
    }

#pragma unroll
    for (int mt = 0; mt < 2; mt++) {
        int r0 = node0 + wm * 32 + mt * 16 + gid;
        int r1 = r0 + 8;
#pragma unroll
        for (int nt = 0; nt < 4; nt++) {
            int c = wn * 32 + nt * 8 + tig * 2;
            float bx = b1[c], by = b1[c + 1];
            if (r0 < n) {
                float2 v = make_float2(fmaxf(acc[mt][nt].x + bx, 0.f),
                                       fmaxf(acc[mt][nt].y + by, 0.f));
                *(float2*)(g_h + (size_t)r0 * 128 + c) = v;
            }
            if (r1 < n) {
                float2 v = make_float2(fmaxf(acc[mt][nt].z + bx, 0.f),
                                       fmaxf(acc[mt][nt].w + by, 0.f));
                *(float2*)(g_h + (size_t)r1 * 128 + c) = v;
            }
        }
    }
}

// ---------------------------------------------------------------------------
// GEMM 2/3 (layer 2): C[n,64] = g_h[n,128] @ W[128,64]
// MODE 0: C = g_y.  MODE 1: C = out, adds g_agg (already mean) + b2.
// ---------------------------------------------------------------------------
template <int MODE>
__global__ void gemm2_kernel(const float* __restrict__ W,
                             const float* __restrict__ b2,
                             float* __restrict__ Cout, int n) {
    constexpr int BM = 128, BN = 64, KC = 32, KHP = 20;
    __shared__ unsigned sAh[BM * KHP], sAl[BM * KHP];
    __shared__ unsigned sWh[BN * KHP], sWl[BN * KHP];
    const int tid = threadIdx.x;
    const int node0 = blockIdx.x * BM;
    const int warp = tid >> 5;
    const int lane = tid & 31;
    const int wm = warp & 3;
    const int wn = warp >> 2;
    const int gid = lane >> 2;
    const int tig = lane & 3;

    float4 acc[2][4];
#pragma unroll
    for (int mt = 0; mt < 2; mt++)
#pragma unroll
        for (int nt = 0; nt < 4; nt++)
            acc[mt][nt] = make_float4(0.f, 0.f, 0.f, 0.f);

    for (int kc = 0; kc < 128; kc += KC) {
        for (int t = tid; t < BM * (KC / 4); t += 256) {
            int m = t >> 3, kq = t & 7;
            int node = node0 + m;
            float4 v = make_float4(0.f, 0.f, 0.f, 0.f);
            if (node < n)
                v = ((const float4*)(g_h + (size_t)node * 128 + kc))[kq];
            unsigned h0, l0, h1, l1;
            split2(make_float2(v.x, v.y), h0, l0);
            split2(make_float2(v.z, v.w), h1, l1);
            sAh[m * KHP + 2 * kq]     = h0;
            sAl[m * KHP + 2 * kq]     = l0;
            sAh[m * KHP + 2 * kq + 1] = h1;
            sAl[m * KHP + 2 * kq + 1] = l1;
        }
        for (int t = tid; t < (KC / 2) * (BN / 4); t += 256) {
            int k2 = t >> 4;
            int nq = t & 15;
            const float* base = W + (size_t)(kc + 2 * k2) * BN + nq * 4;
            float4 va = *(const float4*)base;
            float4 vb = *(const float4*)(base + BN);
            float av[4] = {va.x, va.y, va.z, va.w};
            float bv[4] = {vb.x, vb.y, vb.z, vb.w};
#pragma unroll
            for (int i = 0; i < 4; i++) {
                unsigned h, l;
                split2(make_float2(av[i], bv[i]), h, l);
                sWh[(nq * 4 + i) * KHP + k2] = h;
                sWl[(nq * 4 + i) * KHP + k2] = l;
            }
        }
        __syncthreads();

#pragma unroll
        for (int k16 = 0; k16 < 2; k16++) {
            const int kh = k16 * 8;
            unsigned ah[2][4], al[2][4], bh[4][2], bl[4][2];
#pragma unroll
            for (int mt = 0; mt < 2; mt++) {
                int r0 = (wm * 32 + mt * 16 + gid) * KHP;
                int r1 = r0 + 8 * KHP;
                ah[mt][0] = sAh[r0 + kh + tig];
                ah[mt][1] = sAh[r1 + kh + tig];
                ah[mt][2] = sAh[r0 + kh + tig + 4];
                ah[mt][3] = sAh[r1 + kh + tig + 4];
                al[mt][0] = sAl[r0 + kh + tig];
                al[mt][1] = sAl[r1 + kh + tig];
                al[mt][2] = sAl[r0 + kh + tig + 4];
                al[mt][3] = sAl[r1 + kh + tig + 4];
            }
#pragma unroll
            for (int nt = 0; nt < 4; nt++) {
                int rn = (wn * 32 + nt * 8 + gid) * KHP;
                bh[nt][0] = sWh[rn + kh + tig];
                bh[nt][1] = sWh[rn + kh + tig + 4];
                bl[nt][0] = sWl[rn + kh + tig];
                bl[nt][1] = sWl[rn + kh + tig + 4];
            }
#pragma unroll
            for (int mt = 0; mt < 2; mt++)
#pragma unroll
                for (int nt = 0; nt < 4; nt++) {
                    mma_bf16(acc[mt][nt], ah[mt], bh[nt]);
                    mma_bf16(acc[mt][nt], ah[mt], bl[nt]);
                    mma_bf16(acc[mt][nt], al[mt], bh[nt]);
                }
        }
        __syncthreads();
    }

    float* C = (MODE == 0) ? (float*)g_y : Cout;
#pragma unroll
    for (int mt = 0; mt < 2; mt++) {
        int r0 = node0 + wm * 32 + mt * 16 + gid;
#pragma unroll
        for (int nt = 0; nt < 4; nt++) {
            int c = wn * 32 + nt * 8 + tig * 2;
#pragma unroll
            for (int half = 0; half < 2; half++) {
                int r = r0 + half * 8;
                if (r >= n) continue;
                float vx = half ? acc[mt][nt].z : acc[mt][nt].x;
                float vy = half ? acc[mt][nt].w : acc[mt][nt].y;
                if (MODE == 1) {
                    float2 ag = *(const float2*)(g_agg + (size_t)r * 64 + c);
                    vx += ag.x + b2[c];
                    vy += ag.y + b2[c + 1];
                }
                *(float2*)(C + (size_t)r * 64 + c) = make_float2(vx, vy);
            }
        }
    }
}

// ---------------------------------------------------------------------------
// launch
// ---------------------------------------------------------------------------
extern "C" void kernel_launch(void* const* d_in, const int* in_sizes, int n_in,
                              void* d_out, int out_size) {
    const float* x   = (const float*)d_in[0];
    const void*  ei  = d_in[1];
    const float* W1l = (const float*)d_in[2];
    const float* W1r = (const float*)d_in[3];
    const float* b1  = (const float*)d_in[4];
    const float* W2l = (const float*)d_in[5];
    const float* W2r = (const float*)d_in[6];
    const float* b2  = (const float*)d_in[7];
    float* out = (float*)d_out;

    const int n  = in_sizes[0] / 128;   // 100000
    const int nE = in_sizes[1] / 2;     // 1600000
    const int nb = (n + 1023) / 1024;   // scan chunks

    detect_kernel<<<1, 32>>>((const int*)ei);
    zero_degi_kernel<<<(n + 255) / 256, 256>>>(n);
    convert_kernel<<<(nE + 255) / 256, 256>>>(ei, nE, n);

    // CSR build: scan degrees -> offsets, then bin edges by dst
    scan1_kernel<<<nb, 1024>>>(n);
    scan2_kernel<<<1, 32>>>(nb);
    scan3_kernel<<<(n + 255) / 256, 256>>>(n, nE);
    bin_kernel<<<(nE + 255) / 256, 256>>>(nE);

    // ---- Layer 1 ----
    {
        long long threads = (long long)n * 32;
        gather_agg_kernel<128, false>
            <<<(unsigned)((threads + 255) / 256), 256>>>(x, n);
    }
    gemm1_kernel<<<(n + 63) / 64, 256>>>(x, W1l, W1r, b1, n);

    // ---- Layer 2 ----
    gemm2_kernel<0><<<(n + 127) / 128, 256>>>(W2l, nullptr, nullptr, n);
    {
        long long threads = (long long)n * 32;
        gather_agg_kernel<64, true>
            <<<(unsigned)((threads + 255) / 256), 256>>>(nullptr, n);
    }
    gemm2_kernel<1><<<(n + 127) / 128, 256>>>(W2r, b2, out, n);
}

// round 13
// speedup vs baseline: 3.1623x; 1.1843x over previous
#include <cuda_runtime.h>
#include <cuda_bf16.h>
#include <cstddef>

#define NN 100000
#define EE 1600000

// Scratch (device globals, referenced directly from device code)
__device__ int      g_degi[NN];
__device__ int      g_off[NN + 1];
__device__ int      g_cur[NN];
__device__ int      g_offL[NN];
__device__ int      g_part[128];
__device__ int      g_srcs[EE];              // dst-binned source indices
__device__ int2     g_edges[EE];             // clamped (src, dst)
__device__ unsigned g_aggh[(size_t)NN * 64]; // mean(x) hi, packed (k,k+1) bf16x2
__device__ unsigned g_aggl[(size_t)NN * 64]; // mean(x) lo
__device__ unsigned g_hh[(size_t)NN * 64];   // h hi (bf16x2 pairs)
__device__ unsigned g_hl[(size_t)NN * 64];   // h lo
__device__ float    g_y[(size_t)NN * 64];    // h @ W2l (fp32)
// Pre-split weights, B-fragment packing: [n][k2] u32 = (W[2k2][n], W[2k2+1][n])
__device__ unsigned g_w1h[128 * 128], g_w1l[128 * 128];   // [W1l;W1r], K=256
__device__ unsigned g_w2h[128 * 64],  g_w2l[128 * 64];    // [W2l|W2r], K=128
__device__ int      g_is64;

// ---------------------------------------------------------------------------
// bf16 split + mma helpers
// ---------------------------------------------------------------------------
__device__ __forceinline__ void split2(float2 v, unsigned& hi, unsigned& lo) {
    __nv_bfloat162 h = __float22bfloat162_rn(v);
    float2 hf = __bfloat1622float2(h);
    __nv_bfloat162 l = __float22bfloat162_rn(make_float2(v.x - hf.x, v.y - hf.y));
    hi = *reinterpret_cast<unsigned*>(&h);
    lo = *reinterpret_cast<unsigned*>(&l);
}
__device__ __forceinline__ void mma_bf16(float4& d, const unsigned a[4],
                                         const unsigned b[2]) {
    asm volatile(
        "mma.sync.aligned.m16n8k16.row.col.f32.bf16.bf16.f32 "
        "{%0,%1,%2,%3}, {%4,%5,%6,%7}, {%8,%9}, {%0,%1,%2,%3};"
        : "+f"(d.x), "+f"(d.y), "+f"(d.z), "+f"(d.w)
        : "r"(a[0]), "r"(a[1]), "r"(a[2]), "r"(a[3]), "r"(b[0]), "r"(b[1]));
}

// ---------------------------------------------------------------------------
// dtype detection
// ---------------------------------------------------------------------------
__global__ void detect_kernel(const int* __restrict__ ei32) {
    if (blockIdx.x == 0 && threadIdx.x == 0) {
        int is64 = 1;
        for (int i = 0; i < 64; i++)
            if (ei32[2 * i + 1] != 0) { is64 = 0; break; }
        g_is64 = is64;
    }
}

__global__ void zero_degi_kernel(int n) {
    int i = blockIdx.x * blockDim.x + threadIdx.x;
    if (i < n) g_degi[i] = 0;
}

// ---------------------------------------------------------------------------
// pre-split weights into B-fragment packing (runs once, 24576 threads)
// ---------------------------------------------------------------------------
__global__ void prepw_kernel(const float* __restrict__ W1lp,
                             const float* __restrict__ W1rp,
                             const float* __restrict__ W2lp,
                             const float* __restrict__ W2rp) {
    int i = blockIdx.x * blockDim.x + threadIdx.x;
    if (i < 128 * 128) {                       // W1: [W1l;W1r], 128 n x 128 k2
        int nn = i >> 7, k2 = i & 127;
        int k = 2 * k2;
        float a, b;
        if (k < 128) { a = W1lp[k * 128 + nn]; b = W1lp[(k + 1) * 128 + nn]; }
        else         { a = W1rp[(k - 128) * 128 + nn]; b = W1rp[(k - 127) * 128 + nn]; }
        unsigned h, l; split2(make_float2(a, b), h, l);
        g_w1h[nn * 128 + k2] = h; g_w1l[nn * 128 + k2] = l;
    } else if (i < 128 * 128 + 128 * 64) {     // W2: [W2l|W2r], 128 n x 64 k2
        int j = i - 128 * 128;
        int nn = j >> 6, k2 = j & 63;
        int k = 2 * k2;
        float a, b;
        if (nn < 64) { a = W2lp[k * 64 + nn]; b = W2lp[(k + 1) * 64 + nn]; }
        else         { a = W2rp[k * 64 + nn - 64]; b = W2rp[(k + 1) * 64 + nn - 64]; }
        unsigned h, l; split2(make_float2(a, b), h, l);
        g_w2h[nn * 64 + k2] = h; g_w2l[nn * 64 + k2] = l;
    }
}

// ---------------------------------------------------------------------------
// edge conversion -> clamped int2, fused int degree count
// ---------------------------------------------------------------------------
__global__ void convert_kernel(const void* __restrict__ ei, int nE, int n) {
    int e = blockIdx.x * blockDim.x + threadIdx.x;
    if (e >= nE) return;
    long long s, d;
    if (g_is64) {
        s = ((const long long*)ei)[e];
        d = ((const long long*)ei)[(size_t)nE + e];
    } else {
        s = ((const int*)ei)[e];
        d = ((const int*)ei)[(size_t)nE + e];
    }
    if (s < 0) s = 0; if (s >= n) s = n - 1;
    if (d < 0) d = 0; if (d >= n) d = n - 1;
    g_edges[e] = make_int2((int)s, (int)d);
    atomicAdd(&g_degi[(int)d], 1);
}

// ---------------------------------------------------------------------------
// 3-phase exclusive prefix scan of g_degi -> g_off (chunk = 1024)
// ---------------------------------------------------------------------------
__global__ void scan1_kernel(int n) {
    __shared__ int s[1024];
    const int tid = threadIdx.x;
    const int i = blockIdx.x * 1024 + tid;
    int v = (i < n) ? g_degi[i] : 0;
    s[tid] = v;
    __syncthreads();
#pragma unroll
    for (int d = 1; d < 1024; d <<= 1) {
        int t = (tid >= d) ? s[tid - d] : 0;
        __syncthreads();
        s[tid] += t;
        __syncthreads();
    }
    if (i < n) g_offL[i] = s[tid] - v;
    if (tid == 1023) g_part[blockIdx.x] = s[1023];
}
__global__ void scan2_kernel(int nb) {
    if (threadIdx.x == 0 && blockIdx.x == 0) {
        int acc = 0;
        for (int b = 0; b < nb; b++) { int t = g_part[b]; g_part[b] = acc; acc += t; }
    }
}
__global__ void scan3_kernel(int n, int nE) {
    int i = blockIdx.x * blockDim.x + threadIdx.x;
    if (i < n) {
        int off = g_offL[i] + g_part[i >> 10];
        g_off[i] = off;
        g_cur[i] = off;
    }
    if (i == 0) g_off[n] = nE;
}

__global__ void bin_kernel(int nE) {
    int e = blockIdx.x * blockDim.x + threadIdx.x;
    if (e >= nE) return;
    int2 ed = g_edges[e];
    int pos = atomicAdd(&g_cur[ed.y], 1);
    g_srcs[pos] = ed.x;
}

// ---------------------------------------------------------------------------
// Layer-1 aggregation: one warp per dst node; mean of x rows, written
// PRE-SPLIT (bf16 hi/lo, k-pair packed) for direct GEMM staging.
// ---------------------------------------------------------------------------
__global__ void gather1_kernel(const float* __restrict__ X, int n) {
    const int gw = (blockIdx.x * blockDim.x + threadIdx.x) >> 5;
    if (gw >= n) return;
    const int lane = threadIdx.x & 31;
    const int beg = g_off[gw], end = g_off[gw + 1];

    float4 acc = make_float4(0.f, 0.f, 0.f, 0.f);
    int j = beg;
    for (; j + 4 <= end; j += 4) {
        int s0 = g_srcs[j], s1 = g_srcs[j + 1];
        int s2 = g_srcs[j + 2], s3 = g_srcs[j + 3];
        float4 v0 = ((const float4*)(X + (size_t)s0 * 128))[lane];
        float4 v1 = ((const float4*)(X + (size_t)s1 * 128))[lane];
        float4 v2 = ((const float4*)(X + (size_t)s2 * 128))[lane];
        float4 v3 = ((const float4*)(X + (size_t)s3 * 128))[lane];
        acc.x += (v0.x + v1.x) + (v2.x + v3.x);
        acc.y += (v0.y + v1.y) + (v2.y + v3.y);
        acc.z += (v0.z + v1.z) + (v2.z + v3.z);
        acc.w += (v0.w + v1.w) + (v2.w + v3.w);
    }
    for (; j < end; j++) {
        float4 v = ((const float4*)(X + (size_t)g_srcs[j] * 128))[lane];
        acc.x += v.x; acc.y += v.y; acc.z += v.z; acc.w += v.w;
    }
    float r = 1.0f / (float)max(end - beg, 1);
    acc.x *= r; acc.y *= r; acc.z *= r; acc.w *= r;
    unsigned h0, l0, h1, l1;
    split2(make_float2(acc.x, acc.y), h0, l0);
    split2(make_float2(acc.z, acc.w), h1, l1);
    size_t base = (size_t)gw * 64 + 2 * lane;
    g_aggh[base] = h0; g_aggh[base + 1] = h1;
    g_aggl[base] = l0; g_aggl[base + 1] = l1;
}

// ---------------------------------------------------------------------------
// Layer-2 aggregation: mean of g_y rows, ACCUMULATED into out (which already
// holds h@W2r + b2 from gemm2c).
// ---------------------------------------------------------------------------
__global__ void gather2_kernel(float* __restrict__ out, int n) {
    const int gw = (blockIdx.x * blockDim.x + threadIdx.x) >> 5;
    if (gw >= n) return;
    const int lane = threadIdx.x & 31;
    const int beg = g_off[gw], end = g_off[gw + 1];

    float2 acc = make_float2(0.f, 0.f);
    int j = beg;
    for (; j + 4 <= end; j += 4) {
        int s0 = g_srcs[j], s1 = g_srcs[j + 1];
        int s2 = g_srcs[j + 2], s3 = g_srcs[j + 3];
        float2 v0 = ((const float2*)(g_y + (size_t)s0 * 64))[lane];
        float2 v1 = ((const float2*)(g_y + (size_t)s1 * 64))[lane];
        float2 v2 = ((const float2*)(g_y + (size_t)s2 * 64))[lane];
        float2 v3 = ((const float2*)(g_y + (size_t)s3 * 64))[lane];
        acc.x += (v0.x + v1.x) + (v2.x + v3.x);
        acc.y += (v0.y + v1.y) + (v2.y + v3.y);
    }
    for (; j < end; j++) {
        float2 v = ((const float2*)(g_y + (size_t)g_srcs[j] * 64))[lane];
        acc.x += v.x; acc.y += v.y;
    }
    float r = 1.0f / (float)max(end - beg, 1);
    float2* p = (float2*)(out + (size_t)gw * 64) + lane;
    float2 o = *p;
    o.x += acc.x * r;
    o.y += acc.y * r;
    *p = o;
}

// ---------------------------------------------------------------------------
// GEMM 1: h = relu([mean(x) | x] @ [W1l;W1r] + b1), written pre-split bf16.
// BM=64, BN=128, K=256, KC=32; smem stride KHP=20 (conflict-free fragments).
// A first half copied from pre-split agg; second half split from x.
// W copied from pre-split g_w1.
// ---------------------------------------------------------------------------
__global__ void gemm1_kernel(const float* __restrict__ x,
                             const float* __restrict__ b1, int n) {
    constexpr int BM = 64, BN = 128, KHP = 20;
    __shared__ unsigned sAh[BM * KHP], sAl[BM * KHP];
    __shared__ unsigned sWh[BN * KHP], sWl[BN * KHP];
    const int tid = threadIdx.x;
    const int node0 = blockIdx.x * BM;
    const int warp = tid >> 5;
    const int lane = tid & 31;
    const int wm = warp & 1;
    const int wn = warp >> 1;
    const int gid = lane >> 2;
    const int tig = lane & 3;

    float4 acc[2][4];
#pragma unroll
    for (int mt = 0; mt < 2; mt++)
#pragma unroll
        for (int nt = 0; nt < 4; nt++)
            acc[mt][nt] = make_float4(0.f, 0.f, 0.f, 0.f);

    for (int kc = 0; kc < 256; kc += 32) {
        const int k2c = kc >> 1;               // 0,16,...,112
        if (kc < 128) {
            // A: copy pre-split agg columns [k2c, k2c+16)
            for (int t = tid; t < BM * 16; t += 256) {
                int m = t >> 4, k2 = t & 15;
                int node = node0 + m;
                unsigned h = 0, l = 0;
                if (node < n) {
                    h = g_aggh[(size_t)node * 64 + k2c + k2];
                    l = g_aggl[(size_t)node * 64 + k2c + k2];
                }
                sAh[m * KHP + k2] = h;
                sAl[m * KHP + k2] = l;
            }
        } else {
            // A: split x columns [kc-128, kc-96)
            const int koff = kc - 128;
            for (int t = tid; t < BM * 8; t += 256) {
                int m = t >> 3, kq = t & 7;
                int node = node0 + m;
                float4 v = make_float4(0.f, 0.f, 0.f, 0.f);
                if (node < n)
                    v = ((const float4*)(x + (size_t)node * 128 + koff))[kq];
                unsigned h0, l0, h1, l1;
                split2(make_float2(v.x, v.y), h0, l0);
                split2(make_float2(v.z, v.w), h1, l1);
                sAh[m * KHP + 2 * kq]     = h0;
                sAl[m * KHP + 2 * kq]     = l0;
                sAh[m * KHP + 2 * kq + 1] = h1;
                sAl[m * KHP + 2 * kq + 1] = l1;
            }
        }
        // W: copy pre-split columns
        for (int t = tid; t < BN * 16; t += 256) {
            int nn = t >> 4, k2 = t & 15;
            sWh[nn * KHP + k2] = g_w1h[nn * 128 + k2c + k2];
            sWl[nn * KHP + k2] = g_w1l[nn * 128 + k2c + k2];
        }
        __syncthreads();

#pragma unroll
        for (int k16 = 0; k16 < 2; k16++) {
            const int kh = k16 * 8;
            unsigned ah[2][4], al[2][4], bh[4][2], bl[4][2];
#pragma unroll
            for (int mt = 0; mt < 2; mt++) {
                int r0 = (wm * 32 + mt * 16 + gid) * KHP;
                int r1 = r0 + 8 * KHP;
                ah[mt][0] = sAh[r0 + kh + tig];
                ah[mt][1] = sAh[r1 + kh + tig];
                ah[mt][2] = sAh[r0 + kh + tig + 4];
                ah[mt][3] = sAh[r1 + kh + tig + 4];
                al[mt][0] = sAl[r0 + kh + tig];
                al[mt][1] = sAl[r1 + kh + tig];
                al[mt][2] = sAl[r0 + kh + tig + 4];
                al[mt][3] = sAl[r1 + kh + tig + 4];
            }
#pragma unroll
            for (int nt = 0; nt < 4; nt++) {
                int rn = (wn * 32 + nt * 8 + gid) * KHP;
                bh[nt][0] = sWh[rn + kh + tig];
                bh[nt][1] = sWh[rn + kh + tig + 4];
                bl[nt][0] = sWl[rn + kh + tig];
                bl[nt][1] = sWl[rn + kh + tig + 4];
            }
#pragma unroll
            for (int mt = 0; mt < 2; mt++)
#pragma unroll
                for (int nt = 0; nt < 4; nt++) {
                    mma_bf16(acc[mt][nt], ah[mt], bh[nt]);
                    mma_bf16(acc[mt][nt], ah[mt], bl[nt]);
                    mma_bf16(acc[mt][nt], al[mt], bh[nt]);
                }
        }
        __syncthreads();
    }

    // epilogue: bias + relu, write h PRE-SPLIT (pairs (c,c+1) = k-pair packing)
#pragma unroll
    for (int mt = 0; mt < 2; mt++) {
        int r0 = node0 + wm * 32 + mt * 16 + gid;
        int r1 = r0 + 8;
#pragma unroll
        for (int nt = 0; nt < 4; nt++) {
            int c = wn * 32 + nt * 8 + tig * 2;
            float bx = b1[c], by = b1[c + 1];
            if (r0 < n) {
                float2 v = make_float2(fmaxf(acc[mt][nt].x + bx, 0.f),
                                       fmaxf(acc[mt][nt].y + by, 0.f));
                unsigned h, l; split2(v, h, l);
                g_hh[(size_t)r0 * 64 + (c >> 1)] = h;
                g_hl[(size_t)r0 * 64 + (c >> 1)] = l;
            }
            if (r1 < n) {
                float2 v = make_float2(fmaxf(acc[mt][nt].z + bx, 0.f),
                                       fmaxf(acc[mt][nt].w + by, 0.f));
                unsigned h, l; split2(v, h, l);
                g_hh[(size_t)r1 * 64 + (c >> 1)] = h;
                g_hl[(size_t)r1 * 64 + (c >> 1)] = l;
            }
        }
    }
}

// ---------------------------------------------------------------------------
// GEMM 2 combined: [y | out_partial] = h @ [W2l | W2r]  (BN=128, K=128)
// cols 0-63  -> g_y (fp32)
// cols 64-127-> out = h@W2r + b2  (gather2 then adds mean(y))
// A copied from pre-split g_hh/g_hl; W from pre-split g_w2.
// ---------------------------------------------------------------------------
__global__ void gemm2c_kernel(const float* __restrict__ b2,
                              float* __restrict__ out, int n) {
    constexpr int BM = 64, BN = 128, KHP = 20;
    __shared__ unsigned sAh[BM * KHP], sAl[BM * KHP];
    __shared__ unsigned sWh[BN * KHP], sWl[BN * KHP];
    const int tid = threadIdx.x;
    const int node0 = blockIdx.x * BM;
    const int warp = tid >> 5;
    const int lane = tid & 31;
    const int wm = warp & 1;
    const int wn = warp >> 1;
    const int gid = lane >> 2;
    const int tig = lane & 3;

    float4 acc[2][4];
#pragma unroll
    for (int mt = 0; mt < 2; mt++)
#pragma unroll
        for (int nt = 0; nt < 4; nt++)
            acc[mt][nt] = make_float4(0.f, 0.f, 0.f, 0.f);

    for (int kc = 0; kc < 128; kc += 32) {
        const int k2c = kc >> 1;               // 0,16,32,48
        for (int t = tid; t < BM * 16; t += 256) {
            int m = t >> 4, k2 = t & 15;
            int node = node0 + m;
            unsigned h = 0, l = 0;
            if (node < n) {
                h = g_hh[(size_t)node * 64 + k2c + k2];
                l = g_hl[(size_t)node * 64 + k2c + k2];
            }
            sAh[m * KHP + k2] = h;
            sAl[m * KHP + k2] = l;
        }
        for (int t = tid; t < BN * 16; t += 256) {
            int nn = t >> 4, k2 = t & 15;
            sWh[nn * KHP + k2] = g_w2h[nn * 64 + k2c + k2];
            sWl[nn * KHP + k2] = g_w2l[nn * 64 + k2c + k2];
        }
        __syncthreads();

#pragma unroll
        for (int k16 = 0; k16 < 2; k16++) {
            const int kh = k16 * 8;
            unsigned ah[2][4], al[2][4], bh[4][2], bl[4][2];
#pragma unroll
            for (int mt = 0; mt < 2; mt++) {
                int r0 = (wm * 32 + mt * 16 + gid) * KHP;
                int r1 = r0 + 8 * KHP;
                ah[mt][0] = sAh[r0 + kh + tig];
                ah[mt][1] = sAh[r1 + kh + tig];
                ah[mt][2] = sAh[r0 + kh + tig + 4];
                ah[mt][3] = sAh[r1 + kh + tig + 4];
                al[mt][0] = sAl[r0 + kh + tig];
                al[mt][1] = sAl[r1 + kh + tig];
                al[mt][2] = sAl[r0 + kh + tig + 4];
                al[mt][3] = sAl[r1 + kh + tig + 4];
            }
#pragma unroll
            for (int nt = 0; nt < 4; nt++) {
                int rn = (wn * 32 + nt * 8 + gid) * KHP;
                bh[nt][0] = sWh[rn + kh + tig];
                bh[nt][1] = sWh[rn + kh + tig + 4];
                bl[nt][0] = sWl[rn + kh + tig];
                bl[nt][1] = sWl[rn + kh + tig + 4];
            }
#pragma unroll
            for (int mt = 0; mt < 2; mt++)
#pragma unroll
                for (int nt = 0; nt < 4; nt++) {
                    mma_bf16(acc[mt][nt], ah[mt], bh[nt]);
                    mma_bf16(acc[mt][nt], ah[mt], bl[nt]);
                    mma_bf16(acc[mt][nt], al[mt], bh[nt]);
                }
        }
        __syncthreads();
    }

    // epilogue: cols < 64 -> g_y; cols >= 64 -> out partial (+b2)
    const bool isY = (wn < 2);                  // warps cover 32-col bands
#pragma unroll
    for (int mt = 0; mt < 2; mt++) {
        int r0 = node0 + wm * 32 + mt * 16 + gid;
#pragma unroll
        for (int nt = 0; nt < 4; nt++) {
            int c = wn * 32 + nt * 8 + tig * 2;
#pragma unroll
            for (int half = 0; half < 2; half++) {
                int r = r0 + half * 8;
                if (r >= n) continue;
                float vx = half ? acc[mt][nt].z : acc[mt][nt].x;
                float vy = half ? acc[mt][nt].w : acc[mt][nt].y;
                if (isY) {
                    *(float2*)(g_y + (size_t)r * 64 + c) = make_float2(vx, vy);
                } else {
                    int co = c - 64;
                    *(float2*)(out + (size_t)r * 64 + co) =
                        make_float2(vx + b2[co], vy + b2[co + 1]);
                }
            }
        }
    }
}

// ---------------------------------------------------------------------------
// launch
// ---------------------------------------------------------------------------
extern "C" void kernel_launch(void* const* d_in, const int* in_sizes, int n_in,
                              void* d_out, int out_size) {
    const float* x   = (const float*)d_in[0];
    const void*  ei  = d_in[1];
    const float* W1l = (const float*)d_in[2];
    const float* W1r = (const float*)d_in[3];
    const float* b1  = (const float*)d_in[4];
    const float* W2l = (const float*)d_in[5];
    const float* W2r = (const float*)d_in[6];
    const float* b2  = (const float*)d_in[7];
    float* out = (float*)d_out;

    const int n  = in_sizes[0] / 128;   // 100000
    const int nE = in_sizes[1] / 2;     // 1600000
    const int nb = (n + 1023) / 1024;

    detect_kernel<<<1, 32>>>((const int*)ei);
    zero_degi_kernel<<<(n + 255) / 256, 256>>>(n);
    prepw_kernel<<<(128 * 128 + 128 * 64 + 255) / 256, 256>>>(W1l, W1r, W2l, W2r);
    convert_kernel<<<(nE + 255) / 256, 256>>>(ei, nE, n);

    scan1_kernel<<<nb, 1024>>>(n);
    scan2_kernel<<<1, 32>>>(nb);
    scan3_kernel<<<(n + 255) / 256, 256>>>(n, nE);
    bin_kernel<<<(nE + 255) / 256, 256>>>(nE);

    // ---- Layer 1 ----
    {
        long long threads = (long long)n * 32;
        gather1_kernel<<<(unsigned)((threads + 255) / 256), 256>>>(x, n);
    }
    gemm1_kernel<<<(n + 63) / 64, 256>>>(x, b1, n);

    // ---- Layer 2 ----
    gemm2c_kernel<<<(n + 63) / 64, 256>>>(b2, out, n);
    {
        long long threads = (long long)n * 32;
        gather2_kernel<<<(unsigned)((threads + 255) / 256), 256>>>(out, n);
    }
}